// round 5
// baseline (speedup 1.0000x reference)
#include <cuda_runtime.h>
#include <cuda_bf16.h>
#include <math.h>

#define N_NODES 50000
#define N_EDGES 800000
#define NH 4
#define FOUT 32
#define FIN 128          // = NH*FOUT
#define LEAKY 0.2f
#define NB_CHUNKS ((N_NODES + 255) / 256)   // 196

// ---------------- device scratch (static, allocation-free) ----------------
__device__ __align__(16) float g_proj[N_NODES * FIN];       // 25.6 MB
__device__ __align__(16) float g_s_src[N_NODES * NH];
__device__ __align__(16) float g_s_trg[N_NODES * NH];
__device__ float g_max;
__device__ int g_total;
__device__ int g_cnt[N_NODES];
__device__ int g_off[N_NODES];
__device__ int g_cur[N_NODES];
__device__ int g_esrc[N_EDGES];

// ---------------- helpers ----------------
__device__ __forceinline__ void atomicMaxFloat(float* addr, float value) {
    if (value >= 0.f) atomicMax((int*)addr, __float_as_int(value));
    else              atomicMin((unsigned int*)addr, __float_as_uint(value));
}

__device__ __forceinline__ unsigned long long ffma2(unsigned long long a,
                                                    unsigned long long b,
                                                    unsigned long long c) {
    unsigned long long d;
    asm("fma.rn.f32x2 %0, %1, %2, %3;" : "=l"(d) : "l"(a), "l"(b), "l"(c));
    return d;
}

// ---------------- kernel: zero counts, reset max/total -------------------
__global__ void k_zero() {
    int i = blockIdx.x * blockDim.x + threadIdx.x;
    if (i < N_NODES) g_cnt[i] = 0;
    if (i == 0) { g_max = __uint_as_float(0xFF800000u); g_total = 0; }
}

// ---------------- kernel: count in-degree --------------------------------
__global__ void k_count(const int* __restrict__ ei, int E) {
    int i = blockIdx.x * blockDim.x + threadIdx.x;
    if (i < E) atomicAdd(&g_cnt[ei[E + i]], 1);
}

// ---------------- kernel: CSR offsets (block scan + global atomic base) --
__global__ void k_offsets() {
    __shared__ int s[256];
    __shared__ int sbase;
    int t = threadIdx.x, i = blockIdx.x * 256 + t;
    int v = (i < N_NODES) ? g_cnt[i] : 0;
    s[t] = v;
    __syncthreads();
#pragma unroll
    for (int o = 1; o < 256; o <<= 1) {
        int u = (t >= o) ? s[t - o] : 0;
        __syncthreads();
        s[t] += u;
        __syncthreads();
    }
    if (t == 255) sbase = atomicAdd(&g_total, s[255]);
    __syncthreads();
    if (i < N_NODES) {
        int off = sbase + s[t] - v;
        g_off[i] = off;
        g_cur[i] = off;
    }
}

// ---------------- kernel: proj = x@W via packed f32x2 FMA ----------------
#define BM 64
#define BK 32
__global__ __launch_bounds__(256) void k_gemm(const float* __restrict__ x,
                                              const float* __restrict__ W,
                                              const float* __restrict__ a_src,
                                              const float* __restrict__ a_trg) {
    __shared__ __align__(16) float2 xs[BM][BK];   // value duplicated in .x/.y -> packed multiplier
    __shared__ __align__(16) float ws[BK][FIN];
    const int tid = threadIdx.x;
    const int ty = tid >> 5;      // 0..7
    const int tx = tid & 31;      // 0..31
    const int row0 = blockIdx.x * BM;

    unsigned long long acc01[8], acc23[8];
#pragma unroll
    for (int i = 0; i < 8; i++) { acc01[i] = 0ull; acc23[i] = 0ull; }

    for (int kc = 0; kc < FIN; kc += BK) {
#pragma unroll
        for (int i = 0; i < (BM * BK) / 256; i++) {      // 8 iters
            int idx = tid + i * 256;
            int r = idx >> 5, k = idx & 31;
            int gr = row0 + r;
            float v = (gr < N_NODES) ? x[gr * FIN + kc + k] : 0.f;
            xs[r][k] = make_float2(v, v);
        }
#pragma unroll
        for (int i = 0; i < (BK * FIN) / 256; i++) {     // 16 iters
            int idx = tid + i * 256;
            int k = idx >> 7, c = idx & 127;
            ws[k][c] = W[(kc + k) * FIN + c];
        }
        __syncthreads();
#pragma unroll
        for (int k = 0; k < BK; k++) {
            double2 bd = *(const double2*)&ws[k][tx * 4];
            unsigned long long b01 = __double_as_longlong(bd.x);
            unsigned long long b23 = __double_as_longlong(bd.y);
#pragma unroll
            for (int i = 0; i < 8; i++) {
                unsigned long long aa =
                    __double_as_longlong(*(const double*)&xs[ty * 8 + i][k]);
                acc01[i] = ffma2(aa, b01, acc01[i]);
                acc23[i] = ffma2(aa, b23, acc23[i]);
            }
        }
        __syncthreads();
    }

    // unpack accumulators
    float acc[8][4];
#pragma unroll
    for (int i = 0; i < 8; i++) {
        acc[i][0] = __uint_as_float((unsigned)(acc01[i] & 0xffffffffu));
        acc[i][1] = __uint_as_float((unsigned)(acc01[i] >> 32));
        acc[i][2] = __uint_as_float((unsigned)(acc23[i] & 0xffffffffu));
        acc[i][3] = __uint_as_float((unsigned)(acc23[i] >> 32));
    }

    const int head = tx >> 3;
    float as[4], at[4];
#pragma unroll
    for (int j = 0; j < 4; j++) {
        int f = (tx * 4 + j) & (FOUT - 1);
        as[j] = __ldg(&a_src[head * FOUT + f]);
        at[j] = __ldg(&a_trg[head * FOUT + f]);
    }
#pragma unroll
    for (int i = 0; i < 8; i++) {
        int gr = row0 + ty * 8 + i;
        if (gr >= N_NODES) continue;
        *(float4*)&g_proj[gr * FIN + tx * 4] = *(float4*)acc[i];
        float ps = acc[i][0] * as[0] + acc[i][1] * as[1] + acc[i][2] * as[2] + acc[i][3] * as[3];
        float pt = acc[i][0] * at[0] + acc[i][1] * at[1] + acc[i][2] * at[2] + acc[i][3] * at[3];
#pragma unroll
        for (int o = 1; o < 8; o <<= 1) {
            ps += __shfl_xor_sync(0xffffffffu, ps, o);
            pt += __shfl_xor_sync(0xffffffffu, pt, o);
        }
        if ((tx & 7) == 0) {
            g_s_src[gr * NH + head] = ps;
            g_s_trg[gr * NH + head] = pt;
        }
    }
}

// ---------------- kernel: scatter edges into CSR + global score max ------
__global__ void k_scatter_max(const int* __restrict__ ei, int E) {
    float m = __uint_as_float(0xFF800000u);
    int i = blockIdx.x * blockDim.x + threadIdx.x;
    if (i < E) {
        int src = ei[i];
        int trg = ei[E + i];
        int pos = atomicAdd(&g_cur[trg], 1);
        g_esrc[pos] = src;
        float4 ss = *(const float4*)&g_s_src[src * NH];
        float4 st = *(const float4*)&g_s_trg[trg * NH];
        float v;
        v = ss.x + st.x; v = v > 0.f ? v : LEAKY * v; m = fmaxf(m, v);
        v = ss.y + st.y; v = v > 0.f ? v : LEAKY * v; m = fmaxf(m, v);
        v = ss.z + st.z; v = v > 0.f ? v : LEAKY * v; m = fmaxf(m, v);
        v = ss.w + st.w; v = v > 0.f ? v : LEAKY * v; m = fmaxf(m, v);
    }
#pragma unroll
    for (int o = 16; o >= 1; o >>= 1) m = fmaxf(m, __shfl_xor_sync(0xffffffffu, m, o));
    __shared__ float sm[8];
    int lane = threadIdx.x & 31, warp = threadIdx.x >> 5;
    if (lane == 0) sm[warp] = m;
    __syncthreads();
    if (warp == 0) {
        m = (lane < 8) ? sm[lane] : __uint_as_float(0xFF800000u);
#pragma unroll
        for (int o = 4; o >= 1; o >>= 1) m = fmaxf(m, __shfl_xor_sync(0xffffffffu, m, o));
        if (lane == 0) atomicMaxFloat(&g_max, m);
    }
}

// ---------------- kernel: node-centric aggregate + skip + bias + ELU -----
__global__ __launch_bounds__(256) void k_node(const float* __restrict__ x,
                                              const float* __restrict__ bias,
                                              float* __restrict__ out) {
    int n = (blockIdx.x * blockDim.x + threadIdx.x) >> 5;
    if (n >= N_NODES) return;
    const int lane = threadIdx.x & 31;
    const int head = lane >> 3;
    const int start = g_off[n];
    const int deg = g_cnt[n];
    const float gm = g_max;
    float4 st4 = *(const float4*)&g_s_trg[n * NH];

    // pass 1: per-head softmax denominator
    float d0 = 0.f, d1 = 0.f, d2 = 0.f, d3 = 0.f;
    for (int k = lane; k < deg; k += 32) {
        int src = g_esrc[start + k];
        float4 ss = *(const float4*)&g_s_src[src * NH];
        float v;
        v = ss.x + st4.x; v = v > 0.f ? v : LEAKY * v; d0 += expf(v - gm);
        v = ss.y + st4.y; v = v > 0.f ? v : LEAKY * v; d1 += expf(v - gm);
        v = ss.z + st4.z; v = v > 0.f ? v : LEAKY * v; d2 += expf(v - gm);
        v = ss.w + st4.w; v = v > 0.f ? v : LEAKY * v; d3 += expf(v - gm);
    }
#pragma unroll
    for (int o = 16; o >= 1; o >>= 1) {
        d0 += __shfl_xor_sync(0xffffffffu, d0, o);
        d1 += __shfl_xor_sync(0xffffffffu, d1, o);
        d2 += __shfl_xor_sync(0xffffffffu, d2, o);
        d3 += __shfl_xor_sync(0xffffffffu, d3, o);
    }
    float denom = (head == 0) ? d0 : (head == 1) ? d1 : (head == 2) ? d2 : d3;
    const float rdenom = 1.f / (denom + 1e-16f);
    const float st_h = (head == 0) ? st4.x : (head == 1) ? st4.y : (head == 2) ? st4.z : st4.w;

    // pass 2: attention-weighted gather of proj[src]
    float4 acc = make_float4(0.f, 0.f, 0.f, 0.f);
    if (deg > 0) {
        int src = g_esrc[start];
        for (int k = 0; k < deg; k++) {
            int nsrc = (k + 1 < deg) ? g_esrc[start + k + 1] : 0;   // prefetch
            float s = g_s_src[src * NH + head];
            float v = s + st_h; v = v > 0.f ? v : LEAKY * v;
            float att = expf(v - gm) * rdenom;
            float4 p = *(const float4*)&g_proj[src * FIN + lane * 4];
            acc.x = fmaf(p.x, att, acc.x);
            acc.y = fmaf(p.y, att, acc.y);
            acc.z = fmaf(p.z, att, acc.z);
            acc.w = fmaf(p.w, att, acc.w);
            src = nsrc;
        }
    }

    // epilogue: skip + bias + ELU
    float4 xb = *(const float4*)&x[n * FIN + lane * 4];
    float4 bb = *(const float4*)&bias[lane * 4];
    float4 r;
    r.x = acc.x + xb.x + bb.x; r.x = r.x > 0.f ? r.x : expm1f(r.x);
    r.y = acc.y + xb.y + bb.y; r.y = r.y > 0.f ? r.y : expm1f(r.y);
    r.z = acc.z + xb.z + bb.z; r.z = r.z > 0.f ? r.z : expm1f(r.z);
    r.w = acc.w + xb.w + bb.w; r.w = r.w > 0.f ? r.w : expm1f(r.w);
    *(float4*)&out[n * FIN + lane * 4] = r;
}

// ---------------- launch -------------------------------------------------
extern "C" void kernel_launch(void* const* d_in, const int* in_sizes, int n_in,
                              void* d_out, int out_size) {
    const float* x     = (const float*)d_in[0];
    const int*   ei    = (const int*)d_in[1];   // JAX x64 disabled: int32
    const float* W     = (const float*)d_in[2];
    const float* a_src = (const float*)d_in[3];
    const float* a_trg = (const float*)d_in[4];
    const float* bias  = (const float*)d_in[5];
    float* out = (float*)d_out;

    const int E = in_sizes[1] / 2;

    k_zero<<<NB_CHUNKS, 256>>>();
    k_count<<<(E + 255) / 256, 256>>>(ei, E);
    k_offsets<<<NB_CHUNKS, 256>>>();
    k_gemm<<<(N_NODES + BM - 1) / BM, 256>>>(x, W, a_src, a_trg);
    k_scatter_max<<<(E + 255) / 256, 256>>>(ei, E);
    k_node<<<(N_NODES * 32 + 255) / 256, 256>>>(x, bias, out);
}

// round 7
// speedup vs baseline: 1.1436x; 1.1436x over previous
#include <cuda_runtime.h>
#include <cuda_bf16.h>
#include <math.h>
#include <stdint.h>

#define N_NODES 50000
#define N_EDGES 800000
#define NH 4
#define FOUT 32
#define FIN 128          // = NH*FOUT
#define LEAKY 0.2f
#define NB_CHUNKS ((N_NODES + 255) / 256)   // 196

// ---------------- device scratch (static, allocation-free) ----------------
__device__ __align__(16) float g_proj[N_NODES * FIN];       // 25.6 MB
__device__ __align__(16) float g_s_src[N_NODES * NH];
__device__ __align__(16) float g_s_trg[N_NODES * NH];
__device__ float g_max;
__device__ int g_total;
__device__ int g_cnt[N_NODES];
__device__ int g_off[N_NODES];
__device__ int g_cur[N_NODES];
__device__ int g_esrc[N_EDGES];
// bf16 hi/lo images of B = W^T, laid out [n][k] row-major (unpadded)
__device__ __align__(16) unsigned short g_Bhi[FIN * FIN];
__device__ __align__(16) unsigned short g_Blo[FIN * FIN];

// ---------------- helpers ----------------
__device__ __forceinline__ void atomicMaxFloat(float* addr, float value) {
    if (value >= 0.f) atomicMax((int*)addr, __float_as_int(value));
    else              atomicMin((unsigned int*)addr, __float_as_uint(value));
}

__device__ __forceinline__ void mma16816(float c[4], const uint32_t a[4], const uint32_t b[2]) {
    asm volatile(
        "mma.sync.aligned.m16n8k16.row.col.f32.bf16.bf16.f32 "
        "{%0,%1,%2,%3}, {%4,%5,%6,%7}, {%8,%9}, {%0,%1,%2,%3};"
        : "+f"(c[0]), "+f"(c[1]), "+f"(c[2]), "+f"(c[3])
        : "r"(a[0]), "r"(a[1]), "r"(a[2]), "r"(a[3]), "r"(b[0]), "r"(b[1]));
}

// ---------------- kernel: zero counts, reset max/total -------------------
__global__ void k_zero() {
    int i = blockIdx.x * blockDim.x + threadIdx.x;
    if (i < N_NODES) g_cnt[i] = 0;
    if (i == 0) { g_max = __uint_as_float(0xFF800000u); g_total = 0; }
}

// ---------------- kernel: count in-degree --------------------------------
__global__ void k_count(const int* __restrict__ ei, int E) {
    int i = blockIdx.x * blockDim.x + threadIdx.x;
    if (i < E) atomicAdd(&g_cnt[ei[E + i]], 1);
}

// ---------------- kernel: CSR offsets ------------------------------------
__global__ void k_offsets() {
    __shared__ int s[256];
    __shared__ int sbase;
    int t = threadIdx.x, i = blockIdx.x * 256 + t;
    int v = (i < N_NODES) ? g_cnt[i] : 0;
    s[t] = v;
    __syncthreads();
#pragma unroll
    for (int o = 1; o < 256; o <<= 1) {
        int u = (t >= o) ? s[t - o] : 0;
        __syncthreads();
        s[t] += u;
        __syncthreads();
    }
    if (t == 255) sbase = atomicAdd(&g_total, s[255]);
    __syncthreads();
    if (i < N_NODES) {
        int off = sbase + s[t] - v;
        g_off[i] = off;
        g_cur[i] = off;
    }
}

// ---------------- kernel: W -> bf16 hi/lo images of B=W^T [n][k] ---------
__global__ void k_wconv(const float* __restrict__ W) {
    int idx = blockIdx.x * blockDim.x + threadIdx.x;
    if (idx >= FIN * FIN) return;
    int k = idx >> 7, n = idx & 127;
    float v = W[idx];                       // W[k][n]
    __nv_bfloat16 hi = __float2bfloat16(v);
    __nv_bfloat16 lo = __float2bfloat16(v - __bfloat162float(hi));
    g_Bhi[n * FIN + k] = __bfloat16_as_ushort(hi);
    g_Blo[n * FIN + k] = __bfloat16_as_ushort(lo);
}

// ---------------- HMMA GEMM: proj = x@W (split bf16), + s_src/s_trg ------
// CTA = 128 rows. 8 warps, warp tile 64x32 (2x4). Padded smem stride 136 halves.
#define PADK 136
#define OFF_A_HI 0
#define OFF_A_LO (128 * PADK * 2)            // 34816
#define OFF_B_HI (OFF_A_LO + 128 * PADK * 2) // 69632
#define OFF_B_LO (OFF_B_HI + 128 * PADK * 2) // 104448
#define GEMM_SMEM (OFF_B_LO + 128 * PADK * 2) // 139264
#define BSTRIDE 133                           // bounce stride (floats), coprime with 32

__global__ __launch_bounds__(256) void k_gemm_mma(const float* __restrict__ x,
                                                  const float* __restrict__ a_src,
                                                  const float* __restrict__ a_trg) {
    extern __shared__ char smem[];
    unsigned short* A_hi = (unsigned short*)(smem + OFF_A_HI);
    unsigned short* A_lo = (unsigned short*)(smem + OFF_A_LO);
    unsigned short* B_hi = (unsigned short*)(smem + OFF_B_HI);
    unsigned short* B_lo = (unsigned short*)(smem + OFF_B_LO);

    const int tid = threadIdx.x;
    const int wid = tid >> 5, lane = tid & 31;
    const int row0 = blockIdx.x * 128;

    // ---- load x tile, split to bf16 hi/lo (padded rows) ----
    for (int idx = tid; idx < 128 * 16; idx += 256) {
        int r = idx >> 4, c8 = idx & 15;
        int gr = row0 + r;
        float v[8];
        if (gr < N_NODES) {
            float4 p0 = *(const float4*)&x[(size_t)gr * FIN + c8 * 8];
            float4 p1 = *(const float4*)&x[(size_t)gr * FIN + c8 * 8 + 4];
            v[0]=p0.x; v[1]=p0.y; v[2]=p0.z; v[3]=p0.w;
            v[4]=p1.x; v[5]=p1.y; v[6]=p1.z; v[7]=p1.w;
        } else {
#pragma unroll
            for (int j = 0; j < 8; j++) v[j] = 0.f;
        }
        uint32_t hp[4], lp[4];
#pragma unroll
        for (int j = 0; j < 4; j++) {
            __nv_bfloat16 h0 = __float2bfloat16(v[2*j]);
            __nv_bfloat16 h1 = __float2bfloat16(v[2*j+1]);
            __nv_bfloat16 l0 = __float2bfloat16(v[2*j]   - __bfloat162float(h0));
            __nv_bfloat16 l1 = __float2bfloat16(v[2*j+1] - __bfloat162float(h1));
            hp[j] = (uint32_t)__bfloat16_as_ushort(h0) | ((uint32_t)__bfloat16_as_ushort(h1) << 16);
            lp[j] = (uint32_t)__bfloat16_as_ushort(l0) | ((uint32_t)__bfloat16_as_ushort(l1) << 16);
        }
        *(uint4*)&A_hi[r * PADK + c8 * 8] = make_uint4(hp[0], hp[1], hp[2], hp[3]);
        *(uint4*)&A_lo[r * PADK + c8 * 8] = make_uint4(lp[0], lp[1], lp[2], lp[3]);
    }
    // ---- copy B images into padded smem ----
    for (int idx = tid; idx < 2048; idx += 256) {
        int n = idx >> 4, q = idx & 15;       // 16 uint4 (=8 halves each) per row
        *(uint4*)&B_hi[n * PADK + q * 8] = *(const uint4*)&g_Bhi[n * FIN + q * 8];
        *(uint4*)&B_lo[n * PADK + q * 8] = *(const uint4*)&g_Blo[n * FIN + q * 8];
    }
    __syncthreads();

    // ---- mainloop: 3 passes (Ahi*Bhi, Ahi*Blo, Alo*Bhi) ----
    const int m0 = (wid & 1) * 64;
    const int n0 = (wid >> 1) * 32;
    const int lr = lane >> 2;                 // 0..7
    const int lc = (lane & 3) * 2;            // 0,2,4,6

    float c[4][4][4];
#pragma unroll
    for (int mi = 0; mi < 4; mi++)
#pragma unroll
        for (int ni = 0; ni < 4; ni++)
#pragma unroll
            for (int r = 0; r < 4; r++) c[mi][ni][r] = 0.f;

#pragma unroll
    for (int p = 0; p < 3; p++) {
        const unsigned short* As = (p == 2) ? A_lo : A_hi;
        const unsigned short* Bs = (p == 1) ? B_lo : B_hi;
#pragma unroll
        for (int ks = 0; ks < 8; ks++) {
            const int k0 = ks * 16;
            uint32_t a[4][4], b[4][2];
#pragma unroll
            for (int mi = 0; mi < 4; mi++) {
                int row = m0 + mi * 16 + lr;
                a[mi][0] = *(const uint32_t*)&As[row * PADK + k0 + lc];
                a[mi][1] = *(const uint32_t*)&As[(row + 8) * PADK + k0 + lc];
                a[mi][2] = *(const uint32_t*)&As[row * PADK + k0 + 8 + lc];
                a[mi][3] = *(const uint32_t*)&As[(row + 8) * PADK + k0 + 8 + lc];
            }
#pragma unroll
            for (int ni = 0; ni < 4; ni++) {
                int nr = n0 + ni * 8 + lr;
                b[ni][0] = *(const uint32_t*)&Bs[nr * PADK + k0 + lc];
                b[ni][1] = *(const uint32_t*)&Bs[nr * PADK + k0 + 8 + lc];
            }
#pragma unroll
            for (int mi = 0; mi < 4; mi++)
#pragma unroll
                for (int ni = 0; ni < 4; ni++)
                    mma16816(c[mi][ni], a[mi], b[ni]);
        }
    }
    __syncthreads();   // done with A/B smem; reuse as bounce

    // ---- bounce accumulators to smem (conflict-safe-ish stride 133) ----
    float* bounce = (float*)smem;             // [128][133] = 68096 B (fits in A region)
#pragma unroll
    for (int mi = 0; mi < 4; mi++) {
        int row = m0 + mi * 16 + lr;
#pragma unroll
        for (int ni = 0; ni < 4; ni++) {
            int col = n0 + ni * 8 + lc;
            bounce[row * BSTRIDE + col]           = c[mi][ni][0];
            bounce[row * BSTRIDE + col + 1]       = c[mi][ni][1];
            bounce[(row + 8) * BSTRIDE + col]     = c[mi][ni][2];
            bounce[(row + 8) * BSTRIDE + col + 1] = c[mi][ni][3];
        }
    }
    __syncthreads();

    // ---- per-row head dots: s_src / s_trg ----
    if (tid < 128) {
        int gr = row0 + tid;
        if (gr < N_NODES) {
            const float* rowp = &bounce[tid * BSTRIDE];
#pragma unroll
            for (int h = 0; h < 4; h++) {
                float ps = 0.f, pt = 0.f;
#pragma unroll
                for (int j = 0; j < 32; j++) {
                    float vv = rowp[h * 32 + j];
                    ps = fmaf(vv, __ldg(&a_src[h * 32 + j]), ps);
                    pt = fmaf(vv, __ldg(&a_trg[h * 32 + j]), pt);
                }
                g_s_src[gr * NH + h] = ps;
                g_s_trg[gr * NH + h] = pt;
            }
        }
    }

    // ---- coalesced proj copy-out ----
    const int valid = min(128, N_NODES - row0);
    for (int idx = tid; idx < valid * 128; idx += 256) {
        int r = idx >> 7, cc = idx & 127;
        g_proj[(size_t)(row0 + r) * FIN + cc] = bounce[r * BSTRIDE + cc];
    }
}

// ---------------- kernel: scatter edges into CSR + global score max ------
__global__ void k_scatter_max(const int* __restrict__ ei, int E) {
    float m = __uint_as_float(0xFF800000u);
    int i = blockIdx.x * blockDim.x + threadIdx.x;
    if (i < E) {
        int src = ei[i];
        int trg = ei[E + i];
        int pos = atomicAdd(&g_cur[trg], 1);
        g_esrc[pos] = src;
        float4 ss = *(const float4*)&g_s_src[src * NH];
        float4 st = *(const float4*)&g_s_trg[trg * NH];
        float v;
        v = ss.x + st.x; v = v > 0.f ? v : LEAKY * v; m = fmaxf(m, v);
        v = ss.y + st.y; v = v > 0.f ? v : LEAKY * v; m = fmaxf(m, v);
        v = ss.z + st.z; v = v > 0.f ? v : LEAKY * v; m = fmaxf(m, v);
        v = ss.w + st.w; v = v > 0.f ? v : LEAKY * v; m = fmaxf(m, v);
    }
#pragma unroll
    for (int o = 16; o >= 1; o >>= 1) m = fmaxf(m, __shfl_xor_sync(0xffffffffu, m, o));
    __shared__ float sm[8];
    int lane = threadIdx.x & 31, warp = threadIdx.x >> 5;
    if (lane == 0) sm[warp] = m;
    __syncthreads();
    if (warp == 0) {
        m = (lane < 8) ? sm[lane] : __uint_as_float(0xFF800000u);
#pragma unroll
        for (int o = 4; o >= 1; o >>= 1) m = fmaxf(m, __shfl_xor_sync(0xffffffffu, m, o));
        if (lane == 0) atomicMaxFloat(&g_max, m);
    }
}

// ---------------- kernel: node-centric aggregate + skip + bias + ELU -----
__global__ __launch_bounds__(256) void k_node(const float* __restrict__ x,
                                              const float* __restrict__ bias,
                                              float* __restrict__ out) {
    int n = (blockIdx.x * blockDim.x + threadIdx.x) >> 5;
    if (n >= N_NODES) return;
    const int lane = threadIdx.x & 31;
    const int head = lane >> 3;
    const int start = g_off[n];
    const int deg = g_cnt[n];
    const float gm = g_max;
    float4 st4 = *(const float4*)&g_s_trg[n * NH];

    float d0 = 0.f, d1 = 0.f, d2 = 0.f, d3 = 0.f;
    for (int k = lane; k < deg; k += 32) {
        int src = g_esrc[start + k];
        float4 ss = *(const float4*)&g_s_src[src * NH];
        float v;
        v = ss.x + st4.x; v = v > 0.f ? v : LEAKY * v; d0 += expf(v - gm);
        v = ss.y + st4.y; v = v > 0.f ? v : LEAKY * v; d1 += expf(v - gm);
        v = ss.z + st4.z; v = v > 0.f ? v : LEAKY * v; d2 += expf(v - gm);
        v = ss.w + st4.w; v = v > 0.f ? v : LEAKY * v; d3 += expf(v - gm);
    }
#pragma unroll
    for (int o = 16; o >= 1; o >>= 1) {
        d0 += __shfl_xor_sync(0xffffffffu, d0, o);
        d1 += __shfl_xor_sync(0xffffffffu, d1, o);
        d2 += __shfl_xor_sync(0xffffffffu, d2, o);
        d3 += __shfl_xor_sync(0xffffffffu, d3, o);
    }
    float denom = (head == 0) ? d0 : (head == 1) ? d1 : (head == 2) ? d2 : d3;
    const float rdenom = 1.f / (denom + 1e-16f);
    const float st_h = (head == 0) ? st4.x : (head == 1) ? st4.y : (head == 2) ? st4.z : st4.w;

    float4 acc = make_float4(0.f, 0.f, 0.f, 0.f);
    if (deg > 0) {
        int src = g_esrc[start];
        for (int k = 0; k < deg; k++) {
            int nsrc = (k + 1 < deg) ? g_esrc[start + k + 1] : 0;
            float s = g_s_src[src * NH + head];
            float v = s + st_h; v = v > 0.f ? v : LEAKY * v;
            float att = expf(v - gm) * rdenom;
            float4 p = *(const float4*)&g_proj[src * FIN + lane * 4];
            acc.x = fmaf(p.x, att, acc.x);
            acc.y = fmaf(p.y, att, acc.y);
            acc.z = fmaf(p.z, att, acc.z);
            acc.w = fmaf(p.w, att, acc.w);
            src = nsrc;
        }
    }

    float4 xb = *(const float4*)&x[n * FIN + lane * 4];
    float4 bb = *(const float4*)&bias[lane * 4];
    float4 r;
    r.x = acc.x + xb.x + bb.x; r.x = r.x > 0.f ? r.x : expm1f(r.x);
    r.y = acc.y + xb.y + bb.y; r.y = r.y > 0.f ? r.y : expm1f(r.y);
    r.z = acc.z + xb.z + bb.z; r.z = r.z > 0.f ? r.z : expm1f(r.z);
    r.w = acc.w + xb.w + bb.w; r.w = r.w > 0.f ? r.w : expm1f(r.w);
    *(float4*)&out[n * FIN + lane * 4] = r;
}

// ---------------- launch -------------------------------------------------
extern "C" void kernel_launch(void* const* d_in, const int* in_sizes, int n_in,
                              void* d_out, int out_size) {
    const float* x     = (const float*)d_in[0];
    const int*   ei    = (const int*)d_in[1];   // JAX x64 disabled: int32
    const float* W     = (const float*)d_in[2];
    const float* a_src = (const float*)d_in[3];
    const float* a_trg = (const float*)d_in[4];
    const float* bias  = (const float*)d_in[5];
    float* out = (float*)d_out;

    const int E = in_sizes[1] / 2;

    cudaFuncSetAttribute(k_gemm_mma, cudaFuncAttributeMaxDynamicSharedMemorySize, GEMM_SMEM);

    k_zero<<<NB_CHUNKS, 256>>>();
    k_count<<<(E + 255) / 256, 256>>>(ei, E);
    k_offsets<<<NB_CHUNKS, 256>>>();
    k_wconv<<<(FIN * FIN + 255) / 256, 256>>>(W);
    k_gemm_mma<<<(N_NODES + 127) / 128, 256, GEMM_SMEM>>>(x, a_src, a_trg);
    k_scatter_max<<<(E + 255) / 256, 256>>>(ei, E);
    k_node<<<(N_NODES * 32 + 255) / 256, 256>>>(x, bias, out);
}

// round 8
// speedup vs baseline: 1.2179x; 1.0649x over previous
#include <cuda_runtime.h>
#include <cuda_bf16.h>
#include <cuda_fp16.h>
#include <math.h>
#include <stdint.h>

#define N_NODES 50000
#define N_EDGES 800000
#define NH 4
#define FOUT 32
#define FIN 128          // = NH*FOUT
#define LEAKY 0.2f
#define NB_CHUNKS ((N_NODES + 255) / 256)   // 196

// ---------------- device scratch (static, allocation-free) ----------------
__device__ __align__(16) __half g_projh[N_NODES * FIN];     // 12.8 MB (fp16 proj)
__device__ __align__(16) float g_s_src[N_NODES * NH];
__device__ __align__(16) float g_s_trg[N_NODES * NH];
__device__ float g_max;
__device__ int g_total;
__device__ int g_cnt[N_NODES];
__device__ int g_off[N_NODES];
__device__ int g_cur[N_NODES];
__device__ int g_esrc[N_EDGES];
// bf16 hi/lo images of B = W^T, laid out [n][k] row-major (unpadded)
__device__ __align__(16) unsigned short g_Bhi[FIN * FIN];
__device__ __align__(16) unsigned short g_Blo[FIN * FIN];

// ---------------- helpers ----------------
__device__ __forceinline__ void atomicMaxFloat(float* addr, float value) {
    if (value >= 0.f) atomicMax((int*)addr, __float_as_int(value));
    else              atomicMin((unsigned int*)addr, __float_as_uint(value));
}

__device__ __forceinline__ void mma16816(float c[4], const uint32_t a[4], const uint32_t b[2]) {
    asm volatile(
        "mma.sync.aligned.m16n8k16.row.col.f32.bf16.bf16.f32 "
        "{%0,%1,%2,%3}, {%4,%5,%6,%7}, {%8,%9}, {%0,%1,%2,%3};"
        : "+f"(c[0]), "+f"(c[1]), "+f"(c[2]), "+f"(c[3])
        : "r"(a[0]), "r"(a[1]), "r"(a[2]), "r"(a[3]), "r"(b[0]), "r"(b[1]));
}

// ---------------- kernel: zero counts + reset max + W conversion ---------
__global__ void k_init(const float* __restrict__ W) {
    int i = blockIdx.x * blockDim.x + threadIdx.x;
    if (i < N_NODES) g_cnt[i] = 0;
    if (i == 0) { g_max = __uint_as_float(0xFF800000u); g_total = 0; }
    if (i < FIN * FIN) {
        int k = i >> 7, n = i & 127;
        float v = W[i];                       // W[k][n]
        __nv_bfloat16 hi = __float2bfloat16(v);
        __nv_bfloat16 lo = __float2bfloat16(v - __bfloat162float(hi));
        g_Bhi[n * FIN + k] = __bfloat16_as_ushort(hi);
        g_Blo[n * FIN + k] = __bfloat16_as_ushort(lo);
    }
}

// ---------------- kernel: count in-degree --------------------------------
__global__ void k_count(const int* __restrict__ ei, int E) {
    int i = blockIdx.x * blockDim.x + threadIdx.x;
    if (i < E) atomicAdd(&g_cnt[ei[E + i]], 1);
}

// ---------------- kernel: CSR offsets ------------------------------------
__global__ void k_offsets() {
    __shared__ int s[256];
    __shared__ int sbase;
    int t = threadIdx.x, i = blockIdx.x * 256 + t;
    int v = (i < N_NODES) ? g_cnt[i] : 0;
    s[t] = v;
    __syncthreads();
#pragma unroll
    for (int o = 1; o < 256; o <<= 1) {
        int u = (t >= o) ? s[t - o] : 0;
        __syncthreads();
        s[t] += u;
        __syncthreads();
    }
    if (t == 255) sbase = atomicAdd(&g_total, s[255]);
    __syncthreads();
    if (i < N_NODES) {
        int off = sbase + s[t] - v;
        g_off[i] = off;
        g_cur[i] = off;
    }
}

// ---------------- HMMA GEMM: proj = x@W (split bf16), + s_src/s_trg ------
// CTA = 128 rows. 8 warps, warp tile 64x32 (2x4). Padded smem stride 136 halves.
#define PADK 136
#define OFF_A_HI 0
#define OFF_A_LO (128 * PADK * 2)            // 34816
#define OFF_B_HI (OFF_A_LO + 128 * PADK * 2) // 69632
#define OFF_B_LO (OFF_B_HI + 128 * PADK * 2) // 104448
#define GEMM_SMEM (OFF_B_LO + 128 * PADK * 2) // 139264
#define BSTRIDE 133                           // bounce stride (floats)

__global__ __launch_bounds__(256) void k_gemm_mma(const float* __restrict__ x,
                                                  const float* __restrict__ a_src,
                                                  const float* __restrict__ a_trg) {
    extern __shared__ char smem[];
    unsigned short* A_hi = (unsigned short*)(smem + OFF_A_HI);
    unsigned short* A_lo = (unsigned short*)(smem + OFF_A_LO);
    unsigned short* B_hi = (unsigned short*)(smem + OFF_B_HI);
    unsigned short* B_lo = (unsigned short*)(smem + OFF_B_LO);

    const int tid = threadIdx.x;
    const int wid = tid >> 5, lane = tid & 31;
    const int row0 = blockIdx.x * 128;

    // ---- load x tile, split to bf16 hi/lo (padded rows) ----
    for (int idx = tid; idx < 128 * 16; idx += 256) {
        int r = idx >> 4, c8 = idx & 15;
        int gr = row0 + r;
        float v[8];
        if (gr < N_NODES) {
            float4 p0 = *(const float4*)&x[(size_t)gr * FIN + c8 * 8];
            float4 p1 = *(const float4*)&x[(size_t)gr * FIN + c8 * 8 + 4];
            v[0]=p0.x; v[1]=p0.y; v[2]=p0.z; v[3]=p0.w;
            v[4]=p1.x; v[5]=p1.y; v[6]=p1.z; v[7]=p1.w;
        } else {
#pragma unroll
            for (int j = 0; j < 8; j++) v[j] = 0.f;
        }
        uint32_t hp[4], lp[4];
#pragma unroll
        for (int j = 0; j < 4; j++) {
            __nv_bfloat16 h0 = __float2bfloat16(v[2*j]);
            __nv_bfloat16 h1 = __float2bfloat16(v[2*j+1]);
            __nv_bfloat16 l0 = __float2bfloat16(v[2*j]   - __bfloat162float(h0));
            __nv_bfloat16 l1 = __float2bfloat16(v[2*j+1] - __bfloat162float(h1));
            hp[j] = (uint32_t)__bfloat16_as_ushort(h0) | ((uint32_t)__bfloat16_as_ushort(h1) << 16);
            lp[j] = (uint32_t)__bfloat16_as_ushort(l0) | ((uint32_t)__bfloat16_as_ushort(l1) << 16);
        }
        *(uint4*)&A_hi[r * PADK + c8 * 8] = make_uint4(hp[0], hp[1], hp[2], hp[3]);
        *(uint4*)&A_lo[r * PADK + c8 * 8] = make_uint4(lp[0], lp[1], lp[2], lp[3]);
    }
    // ---- copy B images into padded smem ----
    for (int idx = tid; idx < 2048; idx += 256) {
        int n = idx >> 4, q = idx & 15;
        *(uint4*)&B_hi[n * PADK + q * 8] = *(const uint4*)&g_Bhi[n * FIN + q * 8];
        *(uint4*)&B_lo[n * PADK + q * 8] = *(const uint4*)&g_Blo[n * FIN + q * 8];
    }
    __syncthreads();

    // ---- mainloop: 3 passes (Ahi*Bhi, Ahi*Blo, Alo*Bhi) ----
    const int m0 = (wid & 1) * 64;
    const int n0 = (wid >> 1) * 32;
    const int lr = lane >> 2;                 // 0..7
    const int lc = (lane & 3) * 2;            // 0,2,4,6

    float c[4][4][4];
#pragma unroll
    for (int mi = 0; mi < 4; mi++)
#pragma unroll
        for (int ni = 0; ni < 4; ni++)
#pragma unroll
            for (int r = 0; r < 4; r++) c[mi][ni][r] = 0.f;

#pragma unroll
    for (int p = 0; p < 3; p++) {
        const unsigned short* As = (p == 2) ? A_lo : A_hi;
        const unsigned short* Bs = (p == 1) ? B_lo : B_hi;
#pragma unroll
        for (int ks = 0; ks < 8; ks++) {
            const int k0 = ks * 16;
            uint32_t a[4][4], b[4][2];
#pragma unroll
            for (int mi = 0; mi < 4; mi++) {
                int row = m0 + mi * 16 + lr;
                a[mi][0] = *(const uint32_t*)&As[row * PADK + k0 + lc];
                a[mi][1] = *(const uint32_t*)&As[(row + 8) * PADK + k0 + lc];
                a[mi][2] = *(const uint32_t*)&As[row * PADK + k0 + 8 + lc];
                a[mi][3] = *(const uint32_t*)&As[(row + 8) * PADK + k0 + 8 + lc];
            }
#pragma unroll
            for (int ni = 0; ni < 4; ni++) {
                int nr = n0 + ni * 8 + lr;
                b[ni][0] = *(const uint32_t*)&Bs[nr * PADK + k0 + lc];
                b[ni][1] = *(const uint32_t*)&Bs[nr * PADK + k0 + 8 + lc];
            }
#pragma unroll
            for (int mi = 0; mi < 4; mi++)
#pragma unroll
                for (int ni = 0; ni < 4; ni++)
                    mma16816(c[mi][ni], a[mi], b[ni]);
        }
    }
    __syncthreads();   // done with A/B smem; reuse as bounce

    // ---- bounce accumulators to smem ----
    float* bounce = (float*)smem;             // [128][133] floats
#pragma unroll
    for (int mi = 0; mi < 4; mi++) {
        int row = m0 + mi * 16 + lr;
#pragma unroll
        for (int ni = 0; ni < 4; ni++) {
            int col = n0 + ni * 8 + lc;
            bounce[row * BSTRIDE + col]           = c[mi][ni][0];
            bounce[row * BSTRIDE + col + 1]       = c[mi][ni][1];
            bounce[(row + 8) * BSTRIDE + col]     = c[mi][ni][2];
            bounce[(row + 8) * BSTRIDE + col + 1] = c[mi][ni][3];
        }
    }
    __syncthreads();

    // ---- per-row head dots: s_src / s_trg ----
    if (tid < 128) {
        int gr = row0 + tid;
        if (gr < N_NODES) {
            const float* rowp = &bounce[tid * BSTRIDE];
#pragma unroll
            for (int h = 0; h < 4; h++) {
                float ps = 0.f, pt = 0.f;
#pragma unroll
                for (int j = 0; j < 32; j++) {
                    float vv = rowp[h * 32 + j];
                    ps = fmaf(vv, __ldg(&a_src[h * 32 + j]), ps);
                    pt = fmaf(vv, __ldg(&a_trg[h * 32 + j]), pt);
                }
                g_s_src[gr * NH + h] = ps;
                g_s_trg[gr * NH + h] = pt;
            }
        }
    }

    // ---- coalesced fp16 proj copy-out ----
    const int valid = min(128, N_NODES - row0);
    for (int idx = tid; idx < valid * 64; idx += 256) {   // 64 half2 per row
        int r = idx >> 6, c2 = idx & 63;
        float2 f = make_float2(bounce[r * BSTRIDE + c2 * 2],
                               bounce[r * BSTRIDE + c2 * 2 + 1]);
        ((__half2*)&g_projh[(size_t)(row0 + r) * FIN])[c2] = __float22half2_rn(f);
    }
}

// ---------------- kernel: scatter edges into CSR + global score max ------
__global__ void k_scatter_max(const int* __restrict__ ei, int E) {
    float m = __uint_as_float(0xFF800000u);
    int i = blockIdx.x * blockDim.x + threadIdx.x;
    if (i < E) {
        int src = ei[i];
        int trg = ei[E + i];
        int pos = atomicAdd(&g_cur[trg], 1);
        g_esrc[pos] = src;
        float4 ss = *(const float4*)&g_s_src[src * NH];
        float4 st = *(const float4*)&g_s_trg[trg * NH];
        float v;
        v = ss.x + st.x; v = v > 0.f ? v : LEAKY * v; m = fmaxf(m, v);
        v = ss.y + st.y; v = v > 0.f ? v : LEAKY * v; m = fmaxf(m, v);
        v = ss.z + st.z; v = v > 0.f ? v : LEAKY * v; m = fmaxf(m, v);
        v = ss.w + st.w; v = v > 0.f ? v : LEAKY * v; m = fmaxf(m, v);
    }
#pragma unroll
    for (int o = 16; o >= 1; o >>= 1) m = fmaxf(m, __shfl_xor_sync(0xffffffffu, m, o));
    __shared__ float sm[8];
    int lane = threadIdx.x & 31, warp = threadIdx.x >> 5;
    if (lane == 0) sm[warp] = m;
    __syncthreads();
    if (warp == 0) {
        m = (lane < 8) ? sm[lane] : __uint_as_float(0xFF800000u);
#pragma unroll
        for (int o = 4; o >= 1; o >>= 1) m = fmaxf(m, __shfl_xor_sync(0xffffffffu, m, o));
        if (lane == 0) atomicMaxFloat(&g_max, m);
    }
}

// ---------------- kernel: node-centric aggregate + skip + bias + ELU -----
__global__ __launch_bounds__(256) void k_node(const float* __restrict__ x,
                                              const float* __restrict__ bias,
                                              float* __restrict__ out) {
    int n = (blockIdx.x * blockDim.x + threadIdx.x) >> 5;
    if (n >= N_NODES) return;
    const int lane = threadIdx.x & 31;
    const int head = lane >> 3;
    const int start = g_off[n];
    const int deg = g_cnt[n];
    const float gm = g_max;
    float4 st4 = *(const float4*)&g_s_trg[n * NH];

    float d0 = 0.f, d1 = 0.f, d2 = 0.f, d3 = 0.f;
    for (int k = lane; k < deg; k += 32) {
        int src = g_esrc[start + k];
        float4 ss = *(const float4*)&g_s_src[src * NH];
        float v;
        v = ss.x + st4.x; v = v > 0.f ? v : LEAKY * v; d0 += expf(v - gm);
        v = ss.y + st4.y; v = v > 0.f ? v : LEAKY * v; d1 += expf(v - gm);
        v = ss.z + st4.z; v = v > 0.f ? v : LEAKY * v; d2 += expf(v - gm);
        v = ss.w + st4.w; v = v > 0.f ? v : LEAKY * v; d3 += expf(v - gm);
    }
#pragma unroll
    for (int o = 16; o >= 1; o >>= 1) {
        d0 += __shfl_xor_sync(0xffffffffu, d0, o);
        d1 += __shfl_xor_sync(0xffffffffu, d1, o);
        d2 += __shfl_xor_sync(0xffffffffu, d2, o);
        d3 += __shfl_xor_sync(0xffffffffu, d3, o);
    }
    float denom = (head == 0) ? d0 : (head == 1) ? d1 : (head == 2) ? d2 : d3;
    const float rdenom = 1.f / (denom + 1e-16f);
    const float st_h = (head == 0) ? st4.x : (head == 1) ? st4.y : (head == 2) ? st4.z : st4.w;

    float4 acc = make_float4(0.f, 0.f, 0.f, 0.f);
    if (deg > 0) {
        int src = g_esrc[start];
        for (int k = 0; k < deg; k++) {
            int nsrc = (k + 1 < deg) ? g_esrc[start + k + 1] : 0;
            float s = g_s_src[src * NH + head];
            float v = s + st_h; v = v > 0.f ? v : LEAKY * v;
            float att = expf(v - gm) * rdenom;
            uint2 hw = *(const uint2*)&g_projh[(size_t)src * FIN + lane * 4];
            float2 p0 = __half22float2(*(const __half2*)&hw.x);
            float2 p1 = __half22float2(*(const __half2*)&hw.y);
            acc.x = fmaf(p0.x, att, acc.x);
            acc.y = fmaf(p0.y, att, acc.y);
            acc.z = fmaf(p1.x, att, acc.z);
            acc.w = fmaf(p1.y, att, acc.w);
            src = nsrc;
        }
    }

    float4 xb = *(const float4*)&x[n * FIN + lane * 4];
    float4 bb = *(const float4*)&bias[lane * 4];
    float4 r;
    r.x = acc.x + xb.x + bb.x; r.x = r.x > 0.f ? r.x : expm1f(r.x);
    r.y = acc.y + xb.y + bb.y; r.y = r.y > 0.f ? r.y : expm1f(r.y);
    r.z = acc.z + xb.z + bb.z; r.z = r.z > 0.f ? r.z : expm1f(r.z);
    r.w = acc.w + xb.w + bb.w; r.w = r.w > 0.f ? r.w : expm1f(r.w);
    *(float4*)&out[n * FIN + lane * 4] = r;
}

// ---------------- launch -------------------------------------------------
extern "C" void kernel_launch(void* const* d_in, const int* in_sizes, int n_in,
                              void* d_out, int out_size) {
    const float* x     = (const float*)d_in[0];
    const int*   ei    = (const int*)d_in[1];   // JAX x64 disabled: int32
    const float* W     = (const float*)d_in[2];
    const float* a_src = (const float*)d_in[3];
    const float* a_trg = (const float*)d_in[4];
    const float* bias  = (const float*)d_in[5];
    float* out = (float*)d_out;

    const int E = in_sizes[1] / 2;

    cudaFuncSetAttribute(k_gemm_mma, cudaFuncAttributeMaxDynamicSharedMemorySize, GEMM_SMEM);

    k_init<<<NB_CHUNKS, 256>>>(W);
    k_count<<<(E + 255) / 256, 256>>>(ei, E);
    k_offsets<<<NB_CHUNKS, 256>>>();
    k_gemm_mma<<<(N_NODES + 127) / 128, 256, GEMM_SMEM>>>(x, a_src, a_trg);
    k_scatter_max<<<(E + 255) / 256, 256>>>(ei, E);
    k_node<<<(N_NODES * 32 + 255) / 256, 256>>>(x, bias, out);
}

// round 9
// speedup vs baseline: 1.2209x; 1.0025x over previous
#include <cuda_runtime.h>
#include <cuda_bf16.h>
#include <cuda_fp16.h>
#include <math.h>
#include <stdint.h>

#define N_NODES 50000
#define N_EDGES 800000
#define NH 4
#define FOUT 32
#define FIN 128          // = NH*FOUT
#define LEAKY 0.2f
#define NB_CHUNKS ((N_NODES + 255) / 256)   // 196

// ---------------- device scratch (static, allocation-free) ----------------
__device__ __align__(16) __half g_projh[N_NODES * FIN];     // 12.8 MB (fp16 proj)
__device__ __align__(16) float g_s_src[N_NODES * NH];
__device__ __align__(16) float g_s_trg[N_NODES * NH];
__device__ float g_max;
__device__ int g_total;
__device__ int g_cnt[N_NODES];
__device__ int g_off[N_NODES];
__device__ int g_cur[N_NODES];
__device__ int g_esrc[N_EDGES];
// bf16 hi/lo images of B = W^T, laid out [n][k] row-major (unpadded)
__device__ __align__(16) unsigned short g_Bhi[FIN * FIN];
__device__ __align__(16) unsigned short g_Blo[FIN * FIN];

// ---------------- helpers ----------------
__device__ __forceinline__ void atomicMaxFloat(float* addr, float value) {
    if (value >= 0.f) atomicMax((int*)addr, __float_as_int(value));
    else              atomicMin((unsigned int*)addr, __float_as_uint(value));
}

__device__ __forceinline__ void mma16816(float c[4], const uint32_t a[4], const uint32_t b[2]) {
    asm volatile(
        "mma.sync.aligned.m16n8k16.row.col.f32.bf16.bf16.f32 "
        "{%0,%1,%2,%3}, {%4,%5,%6,%7}, {%8,%9}, {%0,%1,%2,%3};"
        : "+f"(c[0]), "+f"(c[1]), "+f"(c[2]), "+f"(c[3])
        : "r"(a[0]), "r"(a[1]), "r"(a[2]), "r"(a[3]), "r"(b[0]), "r"(b[1]));
}

// ---------------- kernel: zero counts + reset max + W conversion ---------
__global__ void k_init(const float* __restrict__ W) {
    int i = blockIdx.x * blockDim.x + threadIdx.x;
    if (i < N_NODES) g_cnt[i] = 0;
    if (i == 0) { g_max = __uint_as_float(0xFF800000u); g_total = 0; }
    if (i < FIN * FIN) {
        int k = i >> 7, n = i & 127;
        float v = W[i];                       // W[k][n]
        __nv_bfloat16 hi = __float2bfloat16(v);
        __nv_bfloat16 lo = __float2bfloat16(v - __bfloat162float(hi));
        g_Bhi[n * FIN + k] = __bfloat16_as_ushort(hi);
        g_Blo[n * FIN + k] = __bfloat16_as_ushort(lo);
    }
}

// ---------------- kernel: count in-degree --------------------------------
__global__ void k_count(const int* __restrict__ ei, int E) {
    int i = blockIdx.x * blockDim.x + threadIdx.x;
    if (i < E) atomicAdd(&g_cnt[ei[E + i]], 1);
}

// ---------------- kernel: CSR offsets ------------------------------------
__global__ void k_offsets() {
    __shared__ int s[256];
    __shared__ int sbase;
    int t = threadIdx.x, i = blockIdx.x * 256 + t;
    int v = (i < N_NODES) ? g_cnt[i] : 0;
    s[t] = v;
    __syncthreads();
#pragma unroll
    for (int o = 1; o < 256; o <<= 1) {
        int u = (t >= o) ? s[t - o] : 0;
        __syncthreads();
        s[t] += u;
        __syncthreads();
    }
    if (t == 255) sbase = atomicAdd(&g_total, s[255]);
    __syncthreads();
    if (i < N_NODES) {
        int off = sbase + s[t] - v;
        g_off[i] = off;
        g_cur[i] = off;
    }
}

// ---------------- HMMA GEMM: proj = x@W (split bf16), + s_src/s_trg ------
// CTA = 64 rows x 128 cols. 8 warps, warp tile 32x32 (wid&1 -> M, wid>>1 -> N).
// smem ~104 KB -> 2 CTAs/SM; __launch_bounds__(256,2) caps regs at 128.
#define CROWS 64
#define PADK 136
#define OFF_A_HI 0
#define OFF_A_LO (CROWS * PADK * 2)             // 17408
#define OFF_B_HI (OFF_A_LO + CROWS * PADK * 2)  // 34816
#define OFF_B_LO (OFF_B_HI + 128 * PADK * 2)    // 69632
#define GEMM_SMEM (OFF_B_LO + 128 * PADK * 2)   // 104448
#define BSTRIDE 133                              // bounce stride (floats)

__global__ __launch_bounds__(256, 2) void k_gemm_mma(const float* __restrict__ x,
                                                     const float* __restrict__ a_src,
                                                     const float* __restrict__ a_trg) {
    extern __shared__ char smem[];
    unsigned short* A_hi = (unsigned short*)(smem + OFF_A_HI);
    unsigned short* A_lo = (unsigned short*)(smem + OFF_A_LO);
    unsigned short* B_hi = (unsigned short*)(smem + OFF_B_HI);
    unsigned short* B_lo = (unsigned short*)(smem + OFF_B_LO);

    const int tid = threadIdx.x;
    const int wid = tid >> 5, lane = tid & 31;
    const int row0 = blockIdx.x * CROWS;

    // ---- load x tile (64 rows), split to bf16 hi/lo ----
    for (int idx = tid; idx < CROWS * 16; idx += 256) {   // 4 iters
        int r = idx >> 4, c8 = idx & 15;
        int gr = row0 + r;
        float v[8];
        if (gr < N_NODES) {
            float4 p0 = *(const float4*)&x[(size_t)gr * FIN + c8 * 8];
            float4 p1 = *(const float4*)&x[(size_t)gr * FIN + c8 * 8 + 4];
            v[0]=p0.x; v[1]=p0.y; v[2]=p0.z; v[3]=p0.w;
            v[4]=p1.x; v[5]=p1.y; v[6]=p1.z; v[7]=p1.w;
        } else {
#pragma unroll
            for (int j = 0; j < 8; j++) v[j] = 0.f;
        }
        uint32_t hp[4], lp[4];
#pragma unroll
        for (int j = 0; j < 4; j++) {
            __nv_bfloat16 h0 = __float2bfloat16(v[2*j]);
            __nv_bfloat16 h1 = __float2bfloat16(v[2*j+1]);
            __nv_bfloat16 l0 = __float2bfloat16(v[2*j]   - __bfloat162float(h0));
            __nv_bfloat16 l1 = __float2bfloat16(v[2*j+1] - __bfloat162float(h1));
            hp[j] = (uint32_t)__bfloat16_as_ushort(h0) | ((uint32_t)__bfloat16_as_ushort(h1) << 16);
            lp[j] = (uint32_t)__bfloat16_as_ushort(l0) | ((uint32_t)__bfloat16_as_ushort(l1) << 16);
        }
        *(uint4*)&A_hi[r * PADK + c8 * 8] = make_uint4(hp[0], hp[1], hp[2], hp[3]);
        *(uint4*)&A_lo[r * PADK + c8 * 8] = make_uint4(lp[0], lp[1], lp[2], lp[3]);
    }
    // ---- copy B images into padded smem ----
    for (int idx = tid; idx < 2048; idx += 256) {          // 8 iters
        int n = idx >> 4, q = idx & 15;
        *(uint4*)&B_hi[n * PADK + q * 8] = *(const uint4*)&g_Bhi[n * FIN + q * 8];
        *(uint4*)&B_lo[n * PADK + q * 8] = *(const uint4*)&g_Blo[n * FIN + q * 8];
    }
    __syncthreads();

    // ---- mainloop: ks-outer, fragments loaded once, 3 MMA passes --------
    const int m0 = (wid & 1) * 32;
    const int n0 = (wid >> 1) * 32;
    const int lr = lane >> 2;                 // 0..7
    const int lc = (lane & 3) * 2;            // 0,2,4,6

    float c[2][4][4];
#pragma unroll
    for (int mi = 0; mi < 2; mi++)
#pragma unroll
        for (int ni = 0; ni < 4; ni++)
#pragma unroll
            for (int r = 0; r < 4; r++) c[mi][ni][r] = 0.f;

#pragma unroll
    for (int ks = 0; ks < 8; ks++) {
        const int k0 = ks * 16;
        uint32_t ah[2][4], al[2][4], bh[4][2], bl[4][2];
#pragma unroll
        for (int mi = 0; mi < 2; mi++) {
            int row = m0 + mi * 16 + lr;
            ah[mi][0] = *(const uint32_t*)&A_hi[row * PADK + k0 + lc];
            ah[mi][1] = *(const uint32_t*)&A_hi[(row + 8) * PADK + k0 + lc];
            ah[mi][2] = *(const uint32_t*)&A_hi[row * PADK + k0 + 8 + lc];
            ah[mi][3] = *(const uint32_t*)&A_hi[(row + 8) * PADK + k0 + 8 + lc];
            al[mi][0] = *(const uint32_t*)&A_lo[row * PADK + k0 + lc];
            al[mi][1] = *(const uint32_t*)&A_lo[(row + 8) * PADK + k0 + lc];
            al[mi][2] = *(const uint32_t*)&A_lo[row * PADK + k0 + 8 + lc];
            al[mi][3] = *(const uint32_t*)&A_lo[(row + 8) * PADK + k0 + 8 + lc];
        }
#pragma unroll
        for (int ni = 0; ni < 4; ni++) {
            int nr = n0 + ni * 8 + lr;
            bh[ni][0] = *(const uint32_t*)&B_hi[nr * PADK + k0 + lc];
            bh[ni][1] = *(const uint32_t*)&B_hi[nr * PADK + k0 + 8 + lc];
            bl[ni][0] = *(const uint32_t*)&B_lo[nr * PADK + k0 + lc];
            bl[ni][1] = *(const uint32_t*)&B_lo[nr * PADK + k0 + 8 + lc];
        }
#pragma unroll
        for (int mi = 0; mi < 2; mi++)
#pragma unroll
            for (int ni = 0; ni < 4; ni++) {
                mma16816(c[mi][ni], ah[mi], bh[ni]);
                mma16816(c[mi][ni], ah[mi], bl[ni]);
                mma16816(c[mi][ni], al[mi], bh[ni]);
            }
    }
    __syncthreads();   // done with A/B smem; reuse as bounce

    // ---- bounce accumulators to smem ----
    float* bounce = (float*)smem;             // [64][133] floats = 34048 B
#pragma unroll
    for (int mi = 0; mi < 2; mi++) {
        int row = m0 + mi * 16 + lr;
#pragma unroll
        for (int ni = 0; ni < 4; ni++) {
            int col = n0 + ni * 8 + lc;
            bounce[row * BSTRIDE + col]           = c[mi][ni][0];
            bounce[row * BSTRIDE + col + 1]       = c[mi][ni][1];
            bounce[(row + 8) * BSTRIDE + col]     = c[mi][ni][2];
            bounce[(row + 8) * BSTRIDE + col + 1] = c[mi][ni][3];
        }
    }
    __syncthreads();

    // ---- per-row head dots: 4 threads per row, one head each ----
    {
        int r = tid >> 2, h = tid & 3;        // 64 rows x 4 heads = 256 threads
        int gr = row0 + r;
        if (gr < N_NODES) {
            const float* rowp = &bounce[r * BSTRIDE + h * 32];
            float ps = 0.f, pt = 0.f;
#pragma unroll
            for (int j = 0; j < 32; j++) {
                float vv = rowp[j];
                ps = fmaf(vv, __ldg(&a_src[h * 32 + j]), ps);
                pt = fmaf(vv, __ldg(&a_trg[h * 32 + j]), pt);
            }
            g_s_src[gr * NH + h] = ps;
            g_s_trg[gr * NH + h] = pt;
        }
    }

    // ---- coalesced fp16 proj copy-out ----
    const int valid = min(CROWS, N_NODES - row0);
    for (int idx = tid; idx < valid * 64; idx += 256) {   // 64 half2 per row
        int r = idx >> 6, c2 = idx & 63;
        float2 f = make_float2(bounce[r * BSTRIDE + c2 * 2],
                               bounce[r * BSTRIDE + c2 * 2 + 1]);
        ((__half2*)&g_projh[(size_t)(row0 + r) * FIN])[c2] = __float22half2_rn(f);
    }
}

// ---------------- kernel: scatter edges into CSR + global score max ------
__global__ void k_scatter_max(const int* __restrict__ ei, int E) {
    float m = __uint_as_float(0xFF800000u);
    int i = blockIdx.x * blockDim.x + threadIdx.x;
    if (i < E) {
        int src = ei[i];
        int trg = ei[E + i];
        int pos = atomicAdd(&g_cur[trg], 1);
        g_esrc[pos] = src;
        float4 ss = *(const float4*)&g_s_src[src * NH];
        float4 st = *(const float4*)&g_s_trg[trg * NH];
        float v;
        v = ss.x + st.x; v = v > 0.f ? v : LEAKY * v; m = fmaxf(m, v);
        v = ss.y + st.y; v = v > 0.f ? v : LEAKY * v; m = fmaxf(m, v);
        v = ss.z + st.z; v = v > 0.f ? v : LEAKY * v; m = fmaxf(m, v);
        v = ss.w + st.w; v = v > 0.f ? v : LEAKY * v; m = fmaxf(m, v);
    }
#pragma unroll
    for (int o = 16; o >= 1; o >>= 1) m = fmaxf(m, __shfl_xor_sync(0xffffffffu, m, o));
    __shared__ float sm[8];
    int lane = threadIdx.x & 31, warp = threadIdx.x >> 5;
    if (lane == 0) sm[warp] = m;
    __syncthreads();
    if (warp == 0) {
        m = (lane < 8) ? sm[lane] : __uint_as_float(0xFF800000u);
#pragma unroll
        for (int o = 4; o >= 1; o >>= 1) m = fmaxf(m, __shfl_xor_sync(0xffffffffu, m, o));
        if (lane == 0) atomicMaxFloat(&g_max, m);
    }
}

// ---------------- kernel: node-centric aggregate + skip + bias + ELU -----
__global__ __launch_bounds__(256) void k_node(const float* __restrict__ x,
                                              const float* __restrict__ bias,
                                              float* __restrict__ out) {
    int n = (blockIdx.x * blockDim.x + threadIdx.x) >> 5;
    if (n >= N_NODES) return;
    const int lane = threadIdx.x & 31;
    const int head = lane >> 3;
    const int start = g_off[n];
    const int deg = g_cnt[n];
    const float gm = g_max;
    float4 st4 = *(const float4*)&g_s_trg[n * NH];

    float d0 = 0.f, d1 = 0.f, d2 = 0.f, d3 = 0.f;
    for (int k = lane; k < deg; k += 32) {
        int src = g_esrc[start + k];
        float4 ss = *(const float4*)&g_s_src[src * NH];
        float v;
        v = ss.x + st4.x; v = v > 0.f ? v : LEAKY * v; d0 += expf(v - gm);
        v = ss.y + st4.y; v = v > 0.f ? v : LEAKY * v; d1 += expf(v - gm);
        v = ss.z + st4.z; v = v > 0.f ? v : LEAKY * v; d2 += expf(v - gm);
        v = ss.w + st4.w; v = v > 0.f ? v : LEAKY * v; d3 += expf(v - gm);
    }
#pragma unroll
    for (int o = 16; o >= 1; o >>= 1) {
        d0 += __shfl_xor_sync(0xffffffffu, d0, o);
        d1 += __shfl_xor_sync(0xffffffffu, d1, o);
        d2 += __shfl_xor_sync(0xffffffffu, d2, o);
        d3 += __shfl_xor_sync(0xffffffffu, d3, o);
    }
    float denom = (head == 0) ? d0 : (head == 1) ? d1 : (head == 2) ? d2 : d3;
    const float rdenom = 1.f / (denom + 1e-16f);
    const float st_h = (head == 0) ? st4.x : (head == 1) ? st4.y : (head == 2) ? st4.z : st4.w;

    float4 acc = make_float4(0.f, 0.f, 0.f, 0.f);
    if (deg > 0) {
        int src = g_esrc[start];
        for (int k = 0; k < deg; k++) {
            int nsrc = (k + 1 < deg) ? g_esrc[start + k + 1] : 0;
            float s = g_s_src[src * NH + head];
            float v = s + st_h; v = v > 0.f ? v : LEAKY * v;
            float att = expf(v - gm) * rdenom;
            uint2 hw = *(const uint2*)&g_projh[(size_t)src * FIN + lane * 4];
            float2 p0 = __half22float2(*(const __half2*)&hw.x);
            float2 p1 = __half22float2(*(const __half2*)&hw.y);
            acc.x = fmaf(p0.x, att, acc.x);
            acc.y = fmaf(p0.y, att, acc.y);
            acc.z = fmaf(p1.x, att, acc.z);
            acc.w = fmaf(p1.y, att, acc.w);
            src = nsrc;
        }
    }

    float4 xb = *(const float4*)&x[n * FIN + lane * 4];
    float4 bb = *(const float4*)&bias[lane * 4];
    float4 r;
    r.x = acc.x + xb.x + bb.x; r.x = r.x > 0.f ? r.x : expm1f(r.x);
    r.y = acc.y + xb.y + bb.y; r.y = r.y > 0.f ? r.y : expm1f(r.y);
    r.z = acc.z + xb.z + bb.z; r.z = r.z > 0.f ? r.z : expm1f(r.z);
    r.w = acc.w + xb.w + bb.w; r.w = r.w > 0.f ? r.w : expm1f(r.w);
    *(float4*)&out[n * FIN + lane * 4] = r;
}

// ---------------- launch -------------------------------------------------
extern "C" void kernel_launch(void* const* d_in, const int* in_sizes, int n_in,
                              void* d_out, int out_size) {
    const float* x     = (const float*)d_in[0];
    const int*   ei    = (const int*)d_in[1];   // JAX x64 disabled: int32
    const float* W     = (const float*)d_in[2];
    const float* a_src = (const float*)d_in[3];
    const float* a_trg = (const float*)d_in[4];
    const float* bias  = (const float*)d_in[5];
    float* out = (float*)d_out;

    const int E = in_sizes[1] / 2;

    cudaFuncSetAttribute(k_gemm_mma, cudaFuncAttributeMaxDynamicSharedMemorySize, GEMM_SMEM);

    k_init<<<NB_CHUNKS, 256>>>(W);
    k_count<<<(E + 255) / 256, 256>>>(ei, E);
    k_offsets<<<NB_CHUNKS, 256>>>();
    k_gemm_mma<<<(N_NODES + CROWS - 1) / CROWS, 256, GEMM_SMEM>>>(x, a_src, a_trg);
    k_scatter_max<<<(E + 255) / 256, 256>>>(ei, E);
    k_node<<<(N_NODES * 32 + 255) / 256, 256>>>(x, bias, out);
}

// round 10
// speedup vs baseline: 1.2650x; 1.0361x over previous
#include <cuda_runtime.h>
#include <cuda_bf16.h>
#include <cuda_fp16.h>
#include <math.h>
#include <stdint.h>

#define N_NODES 50000
#define N_EDGES 800000
#define NH 4
#define FOUT 32
#define FIN 128          // = NH*FOUT
#define LEAKY 0.2f
#define NB_CHUNKS ((N_NODES + 255) / 256)   // 196

// ---------------- device scratch (static, allocation-free) ----------------
__device__ __align__(16) __half g_projh[N_NODES * FIN];     // 12.8 MB (fp16 proj)
__device__ __align__(16) float g_s_src[N_NODES * NH];
__device__ __align__(16) float g_s_trg[N_NODES * NH];
__device__ float g_max;
__device__ int g_total;
__device__ int g_cnt[N_NODES];
__device__ int g_off[N_NODES];
__device__ int g_cur[N_NODES];
__device__ int g_esrc[N_EDGES];
// bf16 hi/lo images of B = W^T, laid out [n][k] row-major (unpadded)
__device__ __align__(16) unsigned short g_Bhi[FIN * FIN];
__device__ __align__(16) unsigned short g_Blo[FIN * FIN];

// ---------------- helpers ----------------
__device__ __forceinline__ void atomicMaxFloat(float* addr, float value) {
    if (value >= 0.f) atomicMax((int*)addr, __float_as_int(value));
    else              atomicMin((unsigned int*)addr, __float_as_uint(value));
}

__device__ __forceinline__ uint32_t smem_u32(const void* p) {
    uint32_t a;
    asm("{ .reg .u64 t; cvta.to.shared.u64 t, %1; cvt.u32.u64 %0, t; }" : "=r"(a) : "l"(p));
    return a;
}

__device__ __forceinline__ void mma16816(float c[4], const uint32_t a[4], const uint32_t b[2]) {
    asm volatile(
        "mma.sync.aligned.m16n8k16.row.col.f32.bf16.bf16.f32 "
        "{%0,%1,%2,%3}, {%4,%5,%6,%7}, {%8,%9}, {%0,%1,%2,%3};"
        : "+f"(c[0]), "+f"(c[1]), "+f"(c[2]), "+f"(c[3])
        : "r"(a[0]), "r"(a[1]), "r"(a[2]), "r"(a[3]), "r"(b[0]), "r"(b[1]));
}

#define LDSM4(r0, r1, r2, r3, addr) \
    asm volatile("ldmatrix.sync.aligned.m8n8.x4.shared.b16 {%0,%1,%2,%3}, [%4];" \
                 : "=r"(r0), "=r"(r1), "=r"(r2), "=r"(r3) : "r"(addr))

// ---------------- kernel: zero counts + reset max + W conversion ---------
__global__ void k_init(const float* __restrict__ W) {
    int i = blockIdx.x * blockDim.x + threadIdx.x;
    if (i < N_NODES) g_cnt[i] = 0;
    if (i == 0) { g_max = __uint_as_float(0xFF800000u); g_total = 0; }
    if (i < FIN * FIN) {
        int k = i >> 7, n = i & 127;
        float v = W[i];                       // W[k][n]
        __nv_bfloat16 hi = __float2bfloat16(v);
        __nv_bfloat16 lo = __float2bfloat16(v - __bfloat162float(hi));
        g_Bhi[n * FIN + k] = __bfloat16_as_ushort(hi);
        g_Blo[n * FIN + k] = __bfloat16_as_ushort(lo);
    }
}

// ---------------- kernel: count in-degree --------------------------------
__global__ void k_count(const int* __restrict__ ei, int E) {
    int i = blockIdx.x * blockDim.x + threadIdx.x;
    if (i < E) atomicAdd(&g_cnt[ei[E + i]], 1);
}

// ---------------- kernel: CSR offsets ------------------------------------
__global__ void k_offsets() {
    __shared__ int s[256];
    __shared__ int sbase;
    int t = threadIdx.x, i = blockIdx.x * 256 + t;
    int v = (i < N_NODES) ? g_cnt[i] : 0;
    s[t] = v;
    __syncthreads();
#pragma unroll
    for (int o = 1; o < 256; o <<= 1) {
        int u = (t >= o) ? s[t - o] : 0;
        __syncthreads();
        s[t] += u;
        __syncthreads();
    }
    if (t == 255) sbase = atomicAdd(&g_total, s[255]);
    __syncthreads();
    if (i < N_NODES) {
        int off = sbase + s[t] - v;
        g_off[i] = off;
        g_cur[i] = off;
    }
}

// ---------------- HMMA GEMM: proj = x@W (split bf16), + s_src/s_trg ------
// CTA = 64 rows x 128 cols. 8 warps, warp tile 32x32. ldmatrix fragments.
#define CROWS 64
#define PADK 136
#define OFF_A_HI 0
#define OFF_A_LO (CROWS * PADK * 2)             // 17408
#define OFF_B_HI (OFF_A_LO + CROWS * PADK * 2)  // 34816
#define OFF_B_LO (OFF_B_HI + 128 * PADK * 2)    // 69632
#define GEMM_SMEM (OFF_B_LO + 128 * PADK * 2)   // 104448
#define BSTRIDE 133                              // bounce stride (floats)

__global__ __launch_bounds__(256, 2) void k_gemm_mma(const float* __restrict__ x,
                                                     const float* __restrict__ a_src,
                                                     const float* __restrict__ a_trg) {
    extern __shared__ char smem[];
    unsigned short* A_hi = (unsigned short*)(smem + OFF_A_HI);
    unsigned short* A_lo = (unsigned short*)(smem + OFF_A_LO);
    unsigned short* B_hi = (unsigned short*)(smem + OFF_B_HI);
    unsigned short* B_lo = (unsigned short*)(smem + OFF_B_LO);

    const int tid = threadIdx.x;
    const int wid = tid >> 5, lane = tid & 31;
    const int row0 = blockIdx.x * CROWS;

    // ---- load x tile (64 rows), split to bf16 hi/lo ----
    for (int idx = tid; idx < CROWS * 16; idx += 256) {   // 4 iters
        int r = idx >> 4, c8 = idx & 15;
        int gr = row0 + r;
        float v[8];
        if (gr < N_NODES) {
            float4 p0 = *(const float4*)&x[(size_t)gr * FIN + c8 * 8];
            float4 p1 = *(const float4*)&x[(size_t)gr * FIN + c8 * 8 + 4];
            v[0]=p0.x; v[1]=p0.y; v[2]=p0.z; v[3]=p0.w;
            v[4]=p1.x; v[5]=p1.y; v[6]=p1.z; v[7]=p1.w;
        } else {
#pragma unroll
            for (int j = 0; j < 8; j++) v[j] = 0.f;
        }
        uint32_t hp[4], lp[4];
#pragma unroll
        for (int j = 0; j < 4; j++) {
            __nv_bfloat16 h0 = __float2bfloat16(v[2*j]);
            __nv_bfloat16 h1 = __float2bfloat16(v[2*j+1]);
            __nv_bfloat16 l0 = __float2bfloat16(v[2*j]   - __bfloat162float(h0));
            __nv_bfloat16 l1 = __float2bfloat16(v[2*j+1] - __bfloat162float(h1));
            hp[j] = (uint32_t)__bfloat16_as_ushort(h0) | ((uint32_t)__bfloat16_as_ushort(h1) << 16);
            lp[j] = (uint32_t)__bfloat16_as_ushort(l0) | ((uint32_t)__bfloat16_as_ushort(l1) << 16);
        }
        *(uint4*)&A_hi[r * PADK + c8 * 8] = make_uint4(hp[0], hp[1], hp[2], hp[3]);
        *(uint4*)&A_lo[r * PADK + c8 * 8] = make_uint4(lp[0], lp[1], lp[2], lp[3]);
    }
    // ---- copy B images into padded smem ----
    for (int idx = tid; idx < 2048; idx += 256) {          // 8 iters
        int n = idx >> 4, q = idx & 15;
        *(uint4*)&B_hi[n * PADK + q * 8] = *(const uint4*)&g_Bhi[n * FIN + q * 8];
        *(uint4*)&B_lo[n * PADK + q * 8] = *(const uint4*)&g_Blo[n * FIN + q * 8];
    }
    __syncthreads();

    // ---- mainloop: ldmatrix fragments, 3 MMA passes per k-step ----------
    const int m0 = (wid & 1) * 32;
    const int n0 = (wid >> 1) * 32;
    const int lr = lane >> 2;                 // 0..7
    const int lc = (lane & 3) * 2;            // 0,2,4,6

    // per-lane ldmatrix base addresses (bytes)
    const uint32_t sbu = smem_u32(smem);
    const int a_row = m0 + (lane & 15);
    const int a_c8  = (lane >> 4) * 8;
    const uint32_t aH0 = sbu + OFF_A_HI + (uint32_t)(a_row * PADK + a_c8) * 2;
    const uint32_t aL0 = sbu + OFF_A_LO + (uint32_t)(a_row * PADK + a_c8) * 2;
    const int b_row = n0 + ((lane >> 4) << 3) + (lane & 7);
    const int b_c8  = ((lane >> 3) & 1) * 8;
    const uint32_t bH0 = sbu + OFF_B_HI + (uint32_t)(b_row * PADK + b_c8) * 2;
    const uint32_t bL0 = sbu + OFF_B_LO + (uint32_t)(b_row * PADK + b_c8) * 2;
    const uint32_t STEP16 = 16 * PADK * 2;    // +16 rows

    float c[2][4][4];
#pragma unroll
    for (int mi = 0; mi < 2; mi++)
#pragma unroll
        for (int ni = 0; ni < 4; ni++)
#pragma unroll
            for (int r = 0; r < 4; r++) c[mi][ni][r] = 0.f;

#pragma unroll
    for (int ks = 0; ks < 8; ks++) {
        const uint32_t koff = (uint32_t)(ks * 32);   // 16 halves = 32 bytes
        uint32_t ah[2][4], al[2][4], bh[4][2], bl[4][2];
        LDSM4(ah[0][0], ah[0][1], ah[0][2], ah[0][3], aH0 + koff);
        LDSM4(ah[1][0], ah[1][1], ah[1][2], ah[1][3], aH0 + STEP16 + koff);
        LDSM4(al[0][0], al[0][1], al[0][2], al[0][3], aL0 + koff);
        LDSM4(al[1][0], al[1][1], al[1][2], al[1][3], aL0 + STEP16 + koff);
        LDSM4(bh[0][0], bh[0][1], bh[1][0], bh[1][1], bH0 + koff);
        LDSM4(bh[2][0], bh[2][1], bh[3][0], bh[3][1], bH0 + STEP16 + koff);
        LDSM4(bl[0][0], bl[0][1], bl[1][0], bl[1][1], bL0 + koff);
        LDSM4(bl[2][0], bl[2][1], bl[3][0], bl[3][1], bL0 + STEP16 + koff);
#pragma unroll
        for (int mi = 0; mi < 2; mi++)
#pragma unroll
            for (int ni = 0; ni < 4; ni++) {
                mma16816(c[mi][ni], ah[mi], bh[ni]);
                mma16816(c[mi][ni], ah[mi], bl[ni]);
                mma16816(c[mi][ni], al[mi], bh[ni]);
            }
    }
    __syncthreads();   // done with A/B smem; reuse as bounce

    // ---- bounce accumulators to smem ----
    float* bounce = (float*)smem;             // [64][133] floats = 34048 B
#pragma unroll
    for (int mi = 0; mi < 2; mi++) {
        int row = m0 + mi * 16 + lr;
#pragma unroll
        for (int ni = 0; ni < 4; ni++) {
            int col = n0 + ni * 8 + lc;
            bounce[row * BSTRIDE + col]           = c[mi][ni][0];
            bounce[row * BSTRIDE + col + 1]       = c[mi][ni][1];
            bounce[(row + 8) * BSTRIDE + col]     = c[mi][ni][2];
            bounce[(row + 8) * BSTRIDE + col + 1] = c[mi][ni][3];
        }
    }
    __syncthreads();

    // ---- per-row head dots: 4 threads per row, one head each ----
    {
        int r = tid >> 2, h = tid & 3;        // 64 rows x 4 heads
        int gr = row0 + r;
        if (gr < N_NODES) {
            const float* rowp = &bounce[r * BSTRIDE + h * 32];
            float ps = 0.f, pt = 0.f;
#pragma unroll
            for (int j = 0; j < 32; j++) {
                float vv = rowp[j];
                ps = fmaf(vv, __ldg(&a_src[h * 32 + j]), ps);
                pt = fmaf(vv, __ldg(&a_trg[h * 32 + j]), pt);
            }
            g_s_src[gr * NH + h] = ps;
            g_s_trg[gr * NH + h] = pt;
        }
    }

    // ---- coalesced fp16 proj copy-out ----
    const int valid = min(CROWS, N_NODES - row0);
    for (int idx = tid; idx < valid * 64; idx += 256) {   // 64 half2 per row
        int r = idx >> 6, c2 = idx & 63;
        float2 f = make_float2(bounce[r * BSTRIDE + c2 * 2],
                               bounce[r * BSTRIDE + c2 * 2 + 1]);
        ((__half2*)&g_projh[(size_t)(row0 + r) * FIN])[c2] = __float22half2_rn(f);
    }
}

// ---------------- kernel: scatter edges into CSR + global score max ------
__global__ void k_scatter_max(const int* __restrict__ ei, int E) {
    float m = __uint_as_float(0xFF800000u);
    int i = blockIdx.x * blockDim.x + threadIdx.x;
    if (i < E) {
        int src = ei[i];
        int trg = ei[E + i];
        int pos = atomicAdd(&g_cur[trg], 1);
        g_esrc[pos] = src;
        float4 ss = *(const float4*)&g_s_src[src * NH];
        float4 st = *(const float4*)&g_s_trg[trg * NH];
        float v;
        v = ss.x + st.x; v = v > 0.f ? v : LEAKY * v; m = fmaxf(m, v);
        v = ss.y + st.y; v = v > 0.f ? v : LEAKY * v; m = fmaxf(m, v);
        v = ss.z + st.z; v = v > 0.f ? v : LEAKY * v; m = fmaxf(m, v);
        v = ss.w + st.w; v = v > 0.f ? v : LEAKY * v; m = fmaxf(m, v);
    }
#pragma unroll
    for (int o = 16; o >= 1; o >>= 1) m = fmaxf(m, __shfl_xor_sync(0xffffffffu, m, o));
    __shared__ float sm[8];
    int lane = threadIdx.x & 31, warp = threadIdx.x >> 5;
    if (lane == 0) sm[warp] = m;
    __syncthreads();
    if (warp == 0) {
        m = (lane < 8) ? sm[lane] : __uint_as_float(0xFF800000u);
#pragma unroll
        for (int o = 4; o >= 1; o >>= 1) m = fmaxf(m, __shfl_xor_sync(0xffffffffu, m, o));
        if (lane == 0) atomicMaxFloat(&g_max, m);
    }
}

// ---------------- kernel: SINGLE-PASS aggregate + skip + bias + ELU ------
// out = (sum_i exp_i * proj_i) / (sum_i exp_i + 1e-16) + x + bias, then ELU.
// Denominator division is deferred: mathematically identical to reference.
__global__ __launch_bounds__(256) void k_node(const float* __restrict__ x,
                                              const float* __restrict__ bias,
                                              float* __restrict__ out) {
    int n = (blockIdx.x * blockDim.x + threadIdx.x) >> 5;
    if (n >= N_NODES) return;
    const int lane = threadIdx.x & 31;
    const int head = lane >> 3;
    const int start = g_off[n];
    const int deg = g_cnt[n];
    const float gm = g_max;
    const float st_h = g_s_trg[n * NH + head];

    float4 acc = make_float4(0.f, 0.f, 0.f, 0.f);
    float d = 0.f;

    int k = 0;
    int s0 = (deg > 0) ? g_esrc[start] : 0;
    int s1 = (deg > 1) ? g_esrc[start + 1] : 0;
    for (; k + 1 < deg; k += 2) {
        int s2 = (k + 2 < deg) ? g_esrc[start + k + 2] : 0;
        int s3 = (k + 3 < deg) ? g_esrc[start + k + 3] : 0;
        float sa = g_s_src[s0 * NH + head];
        float sb = g_s_src[s1 * NH + head];
        uint2 ha = *(const uint2*)&g_projh[(size_t)s0 * FIN + lane * 4];
        uint2 hb = *(const uint2*)&g_projh[(size_t)s1 * FIN + lane * 4];
        float va = sa + st_h; va = va > 0.f ? va : LEAKY * va;
        float vb = sb + st_h; vb = vb > 0.f ? vb : LEAKY * vb;
        float ea = expf(va - gm);
        float eb = expf(vb - gm);
        d += ea; d += eb;
        float2 pa0 = __half22float2(*(const __half2*)&ha.x);
        float2 pa1 = __half22float2(*(const __half2*)&ha.y);
        float2 pb0 = __half22float2(*(const __half2*)&hb.x);
        float2 pb1 = __half22float2(*(const __half2*)&hb.y);
        acc.x = fmaf(pa0.x, ea, acc.x); acc.x = fmaf(pb0.x, eb, acc.x);
        acc.y = fmaf(pa0.y, ea, acc.y); acc.y = fmaf(pb0.y, eb, acc.y);
        acc.z = fmaf(pa1.x, ea, acc.z); acc.z = fmaf(pb1.x, eb, acc.z);
        acc.w = fmaf(pa1.y, ea, acc.w); acc.w = fmaf(pb1.y, eb, acc.w);
        s0 = s2; s1 = s3;
    }
    if (k < deg) {
        float sa = g_s_src[s0 * NH + head];
        uint2 ha = *(const uint2*)&g_projh[(size_t)s0 * FIN + lane * 4];
        float va = sa + st_h; va = va > 0.f ? va : LEAKY * va;
        float ea = expf(va - gm);
        d += ea;
        float2 pa0 = __half22float2(*(const __half2*)&ha.x);
        float2 pa1 = __half22float2(*(const __half2*)&ha.y);
        acc.x = fmaf(pa0.x, ea, acc.x);
        acc.y = fmaf(pa0.y, ea, acc.y);
        acc.z = fmaf(pa1.x, ea, acc.z);
        acc.w = fmaf(pa1.y, ea, acc.w);
    }

    const float rd = 1.f / (d + 1e-16f);
    float4 xb = *(const float4*)&x[n * FIN + lane * 4];
    float4 bb = *(const float4*)&bias[lane * 4];
    float4 r;
    r.x = fmaf(acc.x, rd, xb.x + bb.x); r.x = r.x > 0.f ? r.x : expm1f(r.x);
    r.y = fmaf(acc.y, rd, xb.y + bb.y); r.y = r.y > 0.f ? r.y : expm1f(r.y);
    r.z = fmaf(acc.z, rd, xb.z + bb.z); r.z = r.z > 0.f ? r.z : expm1f(r.z);
    r.w = fmaf(acc.w, rd, xb.w + bb.w); r.w = r.w > 0.f ? r.w : expm1f(r.w);
    *(float4*)&out[n * FIN + lane * 4] = r;
}

// ---------------- launch -------------------------------------------------
extern "C" void kernel_launch(void* const* d_in, const int* in_sizes, int n_in,
                              void* d_out, int out_size) {
    const float* x     = (const float*)d_in[0];
    const int*   ei    = (const int*)d_in[1];   // JAX x64 disabled: int32
    const float* W     = (const float*)d_in[2];
    const float* a_src = (const float*)d_in[3];
    const float* a_trg = (const float*)d_in[4];
    const float* bias  = (const float*)d_in[5];
    float* out = (float*)d_out;

    const int E = in_sizes[1] / 2;

    cudaFuncSetAttribute(k_gemm_mma, cudaFuncAttributeMaxDynamicSharedMemorySize, GEMM_SMEM);

    k_init<<<NB_CHUNKS, 256>>>(W);
    k_count<<<(E + 255) / 256, 256>>>(ei, E);
    k_offsets<<<NB_CHUNKS, 256>>>();
    k_gemm_mma<<<(N_NODES + CROWS - 1) / CROWS, 256, GEMM_SMEM>>>(x, a_src, a_trg);
    k_scatter_max<<<(E + 255) / 256, 256>>>(ei, E);
    k_node<<<(N_NODES * 32 + 255) / 256, 256>>>(x, bias, out);
}

// round 11
// speedup vs baseline: 1.3209x; 1.0442x over previous
#include <cuda_runtime.h>
#include <cuda_bf16.h>
#include <cuda_fp16.h>
#include <math.h>
#include <stdint.h>

#define N_NODES 50000
#define N_EDGES 800000
#define NH 4
#define FOUT 32
#define FIN 128          // = NH*FOUT
#define LEAKY 0.2f
#define NB_CHUNKS ((N_NODES + 255) / 256)   // 196

// ---------------- device scratch (static, allocation-free) ----------------
__device__ __align__(16) __half g_projh[N_NODES * FIN];     // 12.8 MB (fp16 proj)
__device__ __align__(16) float g_s_src[N_NODES * NH];
__device__ __align__(16) float g_s_trg[N_NODES * NH];
__device__ float g_max;
__device__ int g_total;
__device__ int g_cnt[N_NODES];
__device__ int g_off[N_NODES];
__device__ int g_cur[N_NODES];
__device__ int g_esrc[N_EDGES];
// bf16 hi/lo images of B = W^T, laid out [n][k] row-major (unpadded)
__device__ __align__(16) unsigned short g_Bhi[FIN * FIN];
__device__ __align__(16) unsigned short g_Blo[FIN * FIN];

// ---------------- helpers ----------------
__device__ __forceinline__ void atomicMaxFloat(float* addr, float value) {
    if (value >= 0.f) atomicMax((int*)addr, __float_as_int(value));
    else              atomicMin((unsigned int*)addr, __float_as_uint(value));
}

__device__ __forceinline__ uint32_t smem_u32(const void* p) {
    uint32_t a;
    asm("{ .reg .u64 t; cvta.to.shared.u64 t, %1; cvt.u32.u64 %0, t; }" : "=r"(a) : "l"(p));
    return a;
}

__device__ __forceinline__ void mma16816(float c[4], const uint32_t a[4], const uint32_t b[2]) {
    asm volatile(
        "mma.sync.aligned.m16n8k16.row.col.f32.bf16.bf16.f32 "
        "{%0,%1,%2,%3}, {%4,%5,%6,%7}, {%8,%9}, {%0,%1,%2,%3};"
        : "+f"(c[0]), "+f"(c[1]), "+f"(c[2]), "+f"(c[3])
        : "r"(a[0]), "r"(a[1]), "r"(a[2]), "r"(a[3]), "r"(b[0]), "r"(b[1]));
}

#define LDSM4(r0, r1, r2, r3, addr) \
    asm volatile("ldmatrix.sync.aligned.m8n8.x4.shared.b16 {%0,%1,%2,%3}, [%4];" \
                 : "=r"(r0), "=r"(r1), "=r"(r2), "=r"(r3) : "r"(addr))

// ---------------- kernel: zero counts + reset max + W conversion ---------
__global__ void k_init(const float* __restrict__ W) {
    int i = blockIdx.x * blockDim.x + threadIdx.x;
    if (i < N_NODES) g_cnt[i] = 0;
    if (i == 0) { g_max = __uint_as_float(0xFF800000u); g_total = 0; }
    if (i < FIN * FIN) {
        int k = i >> 7, n = i & 127;
        float v = W[i];                       // W[k][n]
        __nv_bfloat16 hi = __float2bfloat16(v);
        __nv_bfloat16 lo = __float2bfloat16(v - __bfloat162float(hi));
        g_Bhi[n * FIN + k] = __bfloat16_as_ushort(hi);
        g_Blo[n * FIN + k] = __bfloat16_as_ushort(lo);
    }
}

// ---------------- kernel: count in-degree --------------------------------
__global__ void k_count(const int* __restrict__ ei, int E) {
    int i = blockIdx.x * blockDim.x + threadIdx.x;
    if (i < E) atomicAdd(&g_cnt[ei[E + i]], 1);
}

// ---------------- kernel: CSR offsets ------------------------------------
__global__ void k_offsets() {
    __shared__ int s[256];
    __shared__ int sbase;
    int t = threadIdx.x, i = blockIdx.x * 256 + t;
    int v = (i < N_NODES) ? g_cnt[i] : 0;
    s[t] = v;
    __syncthreads();
#pragma unroll
    for (int o = 1; o < 256; o <<= 1) {
        int u = (t >= o) ? s[t - o] : 0;
        __syncthreads();
        s[t] += u;
        __syncthreads();
    }
    if (t == 255) sbase = atomicAdd(&g_total, s[255]);
    __syncthreads();
    if (i < N_NODES) {
        int off = sbase + s[t] - v;
        g_off[i] = off;
        g_cur[i] = off;
    }
}

// ---------------- HMMA GEMM: proj = x@W (split bf16), + s_src/s_trg ------
// CTA = 64 rows x 128 cols. 8 warps, warp tile 32x32. ldmatrix fragments.
// Dual accumulator chains (c1: hi*hi, c2: hi*lo + lo*hi) -> 16 indep chains.
#define CROWS 64
#define PADK 136
#define OFF_A_HI 0
#define OFF_A_LO (CROWS * PADK * 2)             // 17408
#define OFF_B_HI (OFF_A_LO + CROWS * PADK * 2)  // 34816
#define OFF_B_LO (OFF_B_HI + 128 * PADK * 2)    // 69632
#define GEMM_SMEM (OFF_B_LO + 128 * PADK * 2)   // 104448
#define BSTRIDE 133                              // bounce stride (floats)

__global__ __launch_bounds__(256, 2) void k_gemm_mma(const float* __restrict__ x,
                                                     const float* __restrict__ a_src,
                                                     const float* __restrict__ a_trg) {
    extern __shared__ char smem[];
    unsigned short* A_hi = (unsigned short*)(smem + OFF_A_HI);
    unsigned short* A_lo = (unsigned short*)(smem + OFF_A_LO);
    unsigned short* B_hi = (unsigned short*)(smem + OFF_B_HI);
    unsigned short* B_lo = (unsigned short*)(smem + OFF_B_LO);

    const int tid = threadIdx.x;
    const int wid = tid >> 5, lane = tid & 31;
    const int row0 = blockIdx.x * CROWS;

    // ---- load x tile (64 rows), split to bf16 hi/lo ----
    for (int idx = tid; idx < CROWS * 16; idx += 256) {   // 4 iters
        int r = idx >> 4, c8 = idx & 15;
        int gr = row0 + r;
        float v[8];
        if (gr < N_NODES) {
            float4 p0 = *(const float4*)&x[(size_t)gr * FIN + c8 * 8];
            float4 p1 = *(const float4*)&x[(size_t)gr * FIN + c8 * 8 + 4];
            v[0]=p0.x; v[1]=p0.y; v[2]=p0.z; v[3]=p0.w;
            v[4]=p1.x; v[5]=p1.y; v[6]=p1.z; v[7]=p1.w;
        } else {
#pragma unroll
            for (int j = 0; j < 8; j++) v[j] = 0.f;
        }
        uint32_t hp[4], lp[4];
#pragma unroll
        for (int j = 0; j < 4; j++) {
            __nv_bfloat16 h0 = __float2bfloat16(v[2*j]);
            __nv_bfloat16 h1 = __float2bfloat16(v[2*j+1]);
            __nv_bfloat16 l0 = __float2bfloat16(v[2*j]   - __bfloat162float(h0));
            __nv_bfloat16 l1 = __float2bfloat16(v[2*j+1] - __bfloat162float(h1));
            hp[j] = (uint32_t)__bfloat16_as_ushort(h0) | ((uint32_t)__bfloat16_as_ushort(h1) << 16);
            lp[j] = (uint32_t)__bfloat16_as_ushort(l0) | ((uint32_t)__bfloat16_as_ushort(l1) << 16);
        }
        *(uint4*)&A_hi[r * PADK + c8 * 8] = make_uint4(hp[0], hp[1], hp[2], hp[3]);
        *(uint4*)&A_lo[r * PADK + c8 * 8] = make_uint4(lp[0], lp[1], lp[2], lp[3]);
    }
    // ---- copy B images into padded smem ----
    for (int idx = tid; idx < 2048; idx += 256) {          // 8 iters
        int n = idx >> 4, q = idx & 15;
        *(uint4*)&B_hi[n * PADK + q * 8] = *(const uint4*)&g_Bhi[n * FIN + q * 8];
        *(uint4*)&B_lo[n * PADK + q * 8] = *(const uint4*)&g_Blo[n * FIN + q * 8];
    }
    __syncthreads();

    // ---- mainloop: ldmatrix fragments, dual-chain MMA -------------------
    const int m0 = (wid & 1) * 32;
    const int n0 = (wid >> 1) * 32;
    const int lr = lane >> 2;                 // 0..7
    const int lc = (lane & 3) * 2;            // 0,2,4,6

    const uint32_t sbu = smem_u32(smem);
    const int a_row = m0 + (lane & 15);
    const int a_c8  = (lane >> 4) * 8;
    const uint32_t aH0 = sbu + OFF_A_HI + (uint32_t)(a_row * PADK + a_c8) * 2;
    const uint32_t aL0 = sbu + OFF_A_LO + (uint32_t)(a_row * PADK + a_c8) * 2;
    const int b_row = n0 + ((lane >> 4) << 3) + (lane & 7);
    const int b_c8  = ((lane >> 3) & 1) * 8;
    const uint32_t bH0 = sbu + OFF_B_HI + (uint32_t)(b_row * PADK + b_c8) * 2;
    const uint32_t bL0 = sbu + OFF_B_LO + (uint32_t)(b_row * PADK + b_c8) * 2;
    const uint32_t STEP16 = 16 * PADK * 2;    // +16 rows

    float c1[2][4][4], c2[2][4][4];
#pragma unroll
    for (int mi = 0; mi < 2; mi++)
#pragma unroll
        for (int ni = 0; ni < 4; ni++)
#pragma unroll
            for (int r = 0; r < 4; r++) { c1[mi][ni][r] = 0.f; c2[mi][ni][r] = 0.f; }

#pragma unroll
    for (int ks = 0; ks < 8; ks++) {
        const uint32_t koff = (uint32_t)(ks * 32);   // 16 halves = 32 bytes
        uint32_t ah[2][4], al[2][4], bh[4][2], bl[4][2];
        LDSM4(ah[0][0], ah[0][1], ah[0][2], ah[0][3], aH0 + koff);
        LDSM4(ah[1][0], ah[1][1], ah[1][2], ah[1][3], aH0 + STEP16 + koff);
        LDSM4(al[0][0], al[0][1], al[0][2], al[0][3], aL0 + koff);
        LDSM4(al[1][0], al[1][1], al[1][2], al[1][3], aL0 + STEP16 + koff);
        LDSM4(bh[0][0], bh[0][1], bh[1][0], bh[1][1], bH0 + koff);
        LDSM4(bh[2][0], bh[2][1], bh[3][0], bh[3][1], bH0 + STEP16 + koff);
        LDSM4(bl[0][0], bl[0][1], bl[1][0], bl[1][1], bL0 + koff);
        LDSM4(bl[2][0], bl[2][1], bl[3][0], bl[3][1], bL0 + STEP16 + koff);
#pragma unroll
        for (int mi = 0; mi < 2; mi++)
#pragma unroll
            for (int ni = 0; ni < 4; ni++) {
                mma16816(c1[mi][ni], ah[mi], bh[ni]);
                mma16816(c2[mi][ni], ah[mi], bl[ni]);
                mma16816(c2[mi][ni], al[mi], bh[ni]);
            }
    }
    __syncthreads();   // done with A/B smem; reuse as bounce

    // ---- bounce accumulators (c1+c2) to smem ----
    float* bounce = (float*)smem;             // [64][133] floats = 34048 B
#pragma unroll
    for (int mi = 0; mi < 2; mi++) {
        int row = m0 + mi * 16 + lr;
#pragma unroll
        for (int ni = 0; ni < 4; ni++) {
            int col = n0 + ni * 8 + lc;
            bounce[row * BSTRIDE + col]           = c1[mi][ni][0] + c2[mi][ni][0];
            bounce[row * BSTRIDE + col + 1]       = c1[mi][ni][1] + c2[mi][ni][1];
            bounce[(row + 8) * BSTRIDE + col]     = c1[mi][ni][2] + c2[mi][ni][2];
            bounce[(row + 8) * BSTRIDE + col + 1] = c1[mi][ni][3] + c2[mi][ni][3];
        }
    }
    __syncthreads();

    // ---- per-row head dots: 4 threads per row, one head each ----
    {
        int r = tid >> 2, h = tid & 3;        // 64 rows x 4 heads
        int gr = row0 + r;
        if (gr < N_NODES) {
            const float* rowp = &bounce[r * BSTRIDE + h * 32];
            float ps = 0.f, pt = 0.f;
#pragma unroll
            for (int j = 0; j < 32; j++) {
                float vv = rowp[j];
                ps = fmaf(vv, __ldg(&a_src[h * 32 + j]), ps);
                pt = fmaf(vv, __ldg(&a_trg[h * 32 + j]), pt);
            }
            g_s_src[gr * NH + h] = ps;
            g_s_trg[gr * NH + h] = pt;
        }
    }

    // ---- coalesced fp16 proj copy-out ----
    const int valid = min(CROWS, N_NODES - row0);
    for (int idx = tid; idx < valid * 64; idx += 256) {   // 64 half2 per row
        int r = idx >> 6, c2i = idx & 63;
        float2 f = make_float2(bounce[r * BSTRIDE + c2i * 2],
                               bounce[r * BSTRIDE + c2i * 2 + 1]);
        ((__half2*)&g_projh[(size_t)(row0 + r) * FIN])[c2i] = __float22half2_rn(f);
    }
}

// ---------------- kernel: scatter edges into CSR + global score max ------
__global__ void k_scatter_max(const int* __restrict__ ei, int E) {
    float m = __uint_as_float(0xFF800000u);
    int i = blockIdx.x * blockDim.x + threadIdx.x;
    if (i < E) {
        int src = ei[i];
        int trg = ei[E + i];
        int pos = atomicAdd(&g_cur[trg], 1);
        g_esrc[pos] = src;
        float4 ss = *(const float4*)&g_s_src[src * NH];
        float4 st = *(const float4*)&g_s_trg[trg * NH];
        float v;
        v = ss.x + st.x; v = v > 0.f ? v : LEAKY * v; m = fmaxf(m, v);
        v = ss.y + st.y; v = v > 0.f ? v : LEAKY * v; m = fmaxf(m, v);
        v = ss.z + st.z; v = v > 0.f ? v : LEAKY * v; m = fmaxf(m, v);
        v = ss.w + st.w; v = v > 0.f ? v : LEAKY * v; m = fmaxf(m, v);
    }
#pragma unroll
    for (int o = 16; o >= 1; o >>= 1) m = fmaxf(m, __shfl_xor_sync(0xffffffffu, m, o));
    __shared__ float sm[8];
    int lane = threadIdx.x & 31, warp = threadIdx.x >> 5;
    if (lane == 0) sm[warp] = m;
    __syncthreads();
    if (warp == 0) {
        m = (lane < 8) ? sm[lane] : __uint_as_float(0xFF800000u);
#pragma unroll
        for (int o = 4; o >= 1; o >>= 1) m = fmaxf(m, __shfl_xor_sync(0xffffffffu, m, o));
        if (lane == 0) atomicMaxFloat(&g_max, m);
    }
}

// ---------------- kernel: SINGLE-PASS aggregate + skip + bias + ELU ------
__global__ __launch_bounds__(256) void k_node(const float* __restrict__ x,
                                              const float* __restrict__ bias,
                                              float* __restrict__ out) {
    int n = (blockIdx.x * blockDim.x + threadIdx.x) >> 5;
    if (n >= N_NODES) return;
    const int lane = threadIdx.x & 31;
    const int head = lane >> 3;
    const int start = g_off[n];
    const int deg = g_cnt[n];
    const float gm = g_max;
    const float st_h = g_s_trg[n * NH + head];

    float4 acc = make_float4(0.f, 0.f, 0.f, 0.f);
    float d = 0.f;

    int k = 0;
    int s0 = (deg > 0) ? g_esrc[start] : 0;
    int s1 = (deg > 1) ? g_esrc[start + 1] : 0;
    for (; k + 1 < deg; k += 2) {
        int s2 = (k + 2 < deg) ? g_esrc[start + k + 2] : 0;
        int s3 = (k + 3 < deg) ? g_esrc[start + k + 3] : 0;
        float sa = g_s_src[s0 * NH + head];
        float sb = g_s_src[s1 * NH + head];
        uint2 ha = *(const uint2*)&g_projh[(size_t)s0 * FIN + lane * 4];
        uint2 hb = *(const uint2*)&g_projh[(size_t)s1 * FIN + lane * 4];
        float va = sa + st_h; va = va > 0.f ? va : LEAKY * va;
        float vb = sb + st_h; vb = vb > 0.f ? vb : LEAKY * vb;
        float ea = expf(va - gm);
        float eb = expf(vb - gm);
        d += ea; d += eb;
        float2 pa0 = __half22float2(*(const __half2*)&ha.x);
        float2 pa1 = __half22float2(*(const __half2*)&ha.y);
        float2 pb0 = __half22float2(*(const __half2*)&hb.x);
        float2 pb1 = __half22float2(*(const __half2*)&hb.y);
        acc.x = fmaf(pa0.x, ea, acc.x); acc.x = fmaf(pb0.x, eb, acc.x);
        acc.y = fmaf(pa0.y, ea, acc.y); acc.y = fmaf(pb0.y, eb, acc.y);
        acc.z = fmaf(pa1.x, ea, acc.z); acc.z = fmaf(pb1.x, eb, acc.z);
        acc.w = fmaf(pa1.y, ea, acc.w); acc.w = fmaf(pb1.y, eb, acc.w);
        s0 = s2; s1 = s3;
    }
    if (k < deg) {
        float sa = g_s_src[s0 * NH + head];
        uint2 ha = *(const uint2*)&g_projh[(size_t)s0 * FIN + lane * 4];
        float va = sa + st_h; va = va > 0.f ? va : LEAKY * va;
        float ea = expf(va - gm);
        d += ea;
        float2 pa0 = __half22float2(*(const __half2*)&ha.x);
        float2 pa1 = __half22float2(*(const __half2*)&ha.y);
        acc.x = fmaf(pa0.x, ea, acc.x);
        acc.y = fmaf(pa0.y, ea, acc.y);
        acc.z = fmaf(pa1.x, ea, acc.z);
        acc.w = fmaf(pa1.y, ea, acc.w);
    }

    const float rd = 1.f / (d + 1e-16f);
    float4 xb = *(const float4*)&x[n * FIN + lane * 4];
    float4 bb = *(const float4*)&bias[lane * 4];
    float4 r;
    r.x = fmaf(acc.x, rd, xb.x + bb.x); r.x = r.x > 0.f ? r.x : expm1f(r.x);
    r.y = fmaf(acc.y, rd, xb.y + bb.y); r.y = r.y > 0.f ? r.y : expm1f(r.y);
    r.z = fmaf(acc.z, rd, xb.z + bb.z); r.z = r.z > 0.f ? r.z : expm1f(r.z);
    r.w = fmaf(acc.w, rd, xb.w + bb.w); r.w = r.w > 0.f ? r.w : expm1f(r.w);
    *(float4*)&out[n * FIN + lane * 4] = r;
}

// ---------------- launch: graph-forked CSR build || GEMM -----------------
extern "C" void kernel_launch(void* const* d_in, const int* in_sizes, int n_in,
                              void* d_out, int out_size) {
    const float* x     = (const float*)d_in[0];
    const int*   ei    = (const int*)d_in[1];   // JAX x64 disabled: int32
    const float* W     = (const float*)d_in[2];
    const float* a_src = (const float*)d_in[3];
    const float* a_trg = (const float*)d_in[4];
    const float* bias  = (const float*)d_in[5];
    float* out = (float*)d_out;

    const int E = in_sizes[1] / 2;

    static cudaStream_t s2 = nullptr;
    static cudaEvent_t evFork = nullptr, evJoin = nullptr;
    if (s2 == nullptr) {
        cudaStreamCreateWithFlags(&s2, cudaStreamNonBlocking);
        cudaEventCreateWithFlags(&evFork, cudaEventDisableTiming);
        cudaEventCreateWithFlags(&evJoin, cudaEventDisableTiming);
        cudaFuncSetAttribute(k_gemm_mma, cudaFuncAttributeMaxDynamicSharedMemorySize, GEMM_SMEM);
    }

    k_init<<<NB_CHUNKS, 256>>>(W);

    // fork: CSR build on s2, GEMM on main stream
    cudaEventRecord(evFork, 0);
    cudaStreamWaitEvent(s2, evFork, 0);
    k_count<<<(E + 255) / 256, 256, 0, s2>>>(ei, E);
    k_offsets<<<NB_CHUNKS, 256, 0, s2>>>();
    cudaEventRecord(evJoin, s2);

    k_gemm_mma<<<(N_NODES + CROWS - 1) / CROWS, 256, GEMM_SMEM>>>(x, a_src, a_trg);

    // join: scatter needs both CSR offsets and GEMM scores
    cudaStreamWaitEvent(0, evJoin, 0);
    k_scatter_max<<<(E + 255) / 256, 256>>>(ei, E);
    k_node<<<(N_NODES * 32 + 255) / 256, 256>>>(x, bias, out);
}

// round 12
// speedup vs baseline: 1.3479x; 1.0204x over previous
#include <cuda_runtime.h>
#include <cuda_bf16.h>
#include <cuda_fp16.h>
#include <math.h>
#include <stdint.h>

#define N_NODES 50000
#define N_EDGES 800000
#define NH 4
#define FOUT 32
#define FIN 128          // = NH*FOUT
#define LEAKY 0.2f
#define NB_CHUNKS ((N_NODES + 255) / 256)   // 196

// ---------------- device scratch (static, allocation-free) ----------------
__device__ __align__(16) __half g_projh[N_NODES * FIN];     // 12.8 MB (fp16 proj)
__device__ __align__(16) float g_s_src[N_NODES * NH];
__device__ __align__(16) float g_s_trg[N_NODES * NH];
__device__ float g_max;
__device__ int g_total;
__device__ int g_cnt[N_NODES];
__device__ int g_off[N_NODES];
__device__ int g_cur[N_NODES];
__device__ int g_esrc[N_EDGES];
// bf16 hi/lo images of B = W^T, laid out [n][k] row-major (unpadded)
__device__ __align__(16) unsigned short g_Bhi[FIN * FIN];
__device__ __align__(16) unsigned short g_Blo[FIN * FIN];

// ---------------- helpers ----------------
__device__ __forceinline__ void atomicMaxFloat(float* addr, float value) {
    if (value >= 0.f) atomicMax((int*)addr, __float_as_int(value));
    else              atomicMin((unsigned int*)addr, __float_as_uint(value));
}

__device__ __forceinline__ uint32_t smem_u32(const void* p) {
    uint32_t a;
    asm("{ .reg .u64 t; cvta.to.shared.u64 t, %1; cvt.u32.u64 %0, t; }" : "=r"(a) : "l"(p));
    return a;
}

__device__ __forceinline__ void mma16816(float c[4], const uint32_t a[4], const uint32_t b[2]) {
    asm volatile(
        "mma.sync.aligned.m16n8k16.row.col.f32.bf16.bf16.f32 "
        "{%0,%1,%2,%3}, {%4,%5,%6,%7}, {%8,%9}, {%0,%1,%2,%3};"
        : "+f"(c[0]), "+f"(c[1]), "+f"(c[2]), "+f"(c[3])
        : "r"(a[0]), "r"(a[1]), "r"(a[2]), "r"(a[3]), "r"(b[0]), "r"(b[1]));
}

#define LDSM4(r0, r1, r2, r3, addr) \
    asm volatile("ldmatrix.sync.aligned.m8n8.x4.shared.b16 {%0,%1,%2,%3}, [%4];" \
                 : "=r"(r0), "=r"(r1), "=r"(r2), "=r"(r3) : "r"(addr))

// ---------------- kernel: zero counts + reset max + W conversion ---------
__global__ void k_init(const float* __restrict__ W) {
    int i = blockIdx.x * blockDim.x + threadIdx.x;
    if (i < N_NODES) g_cnt[i] = 0;
    if (i == 0) { g_max = __uint_as_float(0xFF800000u); g_total = 0; }
    if (i < FIN * FIN) {
        int k = i >> 7, n = i & 127;
        float v = W[i];                       // W[k][n]
        __nv_bfloat16 hi = __float2bfloat16(v);
        __nv_bfloat16 lo = __float2bfloat16(v - __bfloat162float(hi));
        g_Bhi[n * FIN + k] = __bfloat16_as_ushort(hi);
        g_Blo[n * FIN + k] = __bfloat16_as_ushort(lo);
    }
}

// ---------------- kernel: count in-degree --------------------------------
__global__ void k_count(const int* __restrict__ ei, int E) {
    int i = blockIdx.x * blockDim.x + threadIdx.x;
    if (i < E) atomicAdd(&g_cnt[ei[E + i]], 1);
}

// ---------------- kernel: CSR offsets ------------------------------------
__global__ void k_offsets() {
    __shared__ int s[256];
    __shared__ int sbase;
    int t = threadIdx.x, i = blockIdx.x * 256 + t;
    int v = (i < N_NODES) ? g_cnt[i] : 0;
    s[t] = v;
    __syncthreads();
#pragma unroll
    for (int o = 1; o < 256; o <<= 1) {
        int u = (t >= o) ? s[t - o] : 0;
        __syncthreads();
        s[t] += u;
        __syncthreads();
    }
    if (t == 255) sbase = atomicAdd(&g_total, s[255]);
    __syncthreads();
    if (i < N_NODES) {
        int off = sbase + s[t] - v;
        g_off[i] = off;
        g_cur[i] = off;
    }
}

// ---------------- kernel: scatter edges into CSR (no scores needed) ------
__global__ void k_scatter(const int* __restrict__ ei, int E) {
    int i = blockIdx.x * blockDim.x + threadIdx.x;
    if (i >= E) return;
    int src = ei[i];
    int trg = ei[E + i];
    int pos = atomicAdd(&g_cur[trg], 1);
    g_esrc[pos] = src;
}

// ---------------- HMMA GEMM: proj = x@W (split bf16), + s_src/s_trg ------
// CTA = 64 rows x 64 cols. smem 69.6 KB -> 3 CTAs/SM. 8 warps, warp tile 32x16.
#define CROWS 64
#define CCOLS 64
#define PADK 136
#define OFF_A_HI 0
#define OFF_A_LO (CROWS * PADK * 2)             // 17408
#define OFF_B_HI (OFF_A_LO + CROWS * PADK * 2)  // 34816
#define OFF_B_LO (OFF_B_HI + CCOLS * PADK * 2)  // 52224
#define GEMM_SMEM (OFF_B_LO + CCOLS * PADK * 2) // 69632
#define BSTRIDE 68                               // bounce stride (floats)

__global__ __launch_bounds__(256, 3) void k_gemm_mma(const float* __restrict__ x,
                                                     const float* __restrict__ a_src,
                                                     const float* __restrict__ a_trg) {
    extern __shared__ char smem[];
    unsigned short* A_hi = (unsigned short*)(smem + OFF_A_HI);
    unsigned short* A_lo = (unsigned short*)(smem + OFF_A_LO);
    unsigned short* B_hi = (unsigned short*)(smem + OFF_B_HI);
    unsigned short* B_lo = (unsigned short*)(smem + OFF_B_LO);

    const int tid = threadIdx.x;
    const int wid = tid >> 5, lane = tid & 31;
    const int row0 = blockIdx.x * CROWS;
    const int col0 = blockIdx.y * CCOLS;

    // ---- load x tile (64 rows, full K), split to bf16 hi/lo ----
    for (int idx = tid; idx < CROWS * 16; idx += 256) {   // 4 iters
        int r = idx >> 4, c8 = idx & 15;
        int gr = row0 + r;
        float v[8];
        if (gr < N_NODES) {
            float4 p0 = *(const float4*)&x[(size_t)gr * FIN + c8 * 8];
            float4 p1 = *(const float4*)&x[(size_t)gr * FIN + c8 * 8 + 4];
            v[0]=p0.x; v[1]=p0.y; v[2]=p0.z; v[3]=p0.w;
            v[4]=p1.x; v[5]=p1.y; v[6]=p1.z; v[7]=p1.w;
        } else {
#pragma unroll
            for (int j = 0; j < 8; j++) v[j] = 0.f;
        }
        uint32_t hp[4], lp[4];
#pragma unroll
        for (int j = 0; j < 4; j++) {
            __nv_bfloat16 h0 = __float2bfloat16(v[2*j]);
            __nv_bfloat16 h1 = __float2bfloat16(v[2*j+1]);
            __nv_bfloat16 l0 = __float2bfloat16(v[2*j]   - __bfloat162float(h0));
            __nv_bfloat16 l1 = __float2bfloat16(v[2*j+1] - __bfloat162float(h1));
            hp[j] = (uint32_t)__bfloat16_as_ushort(h0) | ((uint32_t)__bfloat16_as_ushort(h1) << 16);
            lp[j] = (uint32_t)__bfloat16_as_ushort(l0) | ((uint32_t)__bfloat16_as_ushort(l1) << 16);
        }
        *(uint4*)&A_hi[r * PADK + c8 * 8] = make_uint4(hp[0], hp[1], hp[2], hp[3]);
        *(uint4*)&A_lo[r * PADK + c8 * 8] = make_uint4(lp[0], lp[1], lp[2], lp[3]);
    }
    // ---- copy this CTA's 64-col half of B images ----
    for (int idx = tid; idx < 1024; idx += 256) {          // 4 iters x2
        int n = idx >> 4, q = idx & 15;
        *(uint4*)&B_hi[n * PADK + q * 8] = *(const uint4*)&g_Bhi[(col0 + n) * FIN + q * 8];
        *(uint4*)&B_lo[n * PADK + q * 8] = *(const uint4*)&g_Blo[(col0 + n) * FIN + q * 8];
    }
    __syncthreads();

    // ---- mainloop: ldmatrix fragments, 3 passes, single accum chain -----
    const int m0 = (wid & 1) * 32;
    const int n0 = (wid >> 1) * 16;
    const int lr = lane >> 2;                 // 0..7
    const int lc = (lane & 3) * 2;            // 0,2,4,6

    const uint32_t sbu = smem_u32(smem);
    const int a_row = m0 + (lane & 15);
    const int a_c8  = (lane >> 4) * 8;
    const uint32_t aH0 = sbu + OFF_A_HI + (uint32_t)(a_row * PADK + a_c8) * 2;
    const uint32_t aL0 = sbu + OFF_A_LO + (uint32_t)(a_row * PADK + a_c8) * 2;
    const int b_row = n0 + ((lane >> 4) << 3) + (lane & 7);
    const int b_c8  = ((lane >> 3) & 1) * 8;
    const uint32_t bH0 = sbu + OFF_B_HI + (uint32_t)(b_row * PADK + b_c8) * 2;
    const uint32_t bL0 = sbu + OFF_B_LO + (uint32_t)(b_row * PADK + b_c8) * 2;
    const uint32_t STEP16 = 16 * PADK * 2;    // +16 rows

    float c[2][2][4];
#pragma unroll
    for (int mi = 0; mi < 2; mi++)
#pragma unroll
        for (int ni = 0; ni < 2; ni++)
#pragma unroll
            for (int r = 0; r < 4; r++) c[mi][ni][r] = 0.f;

#pragma unroll
    for (int ks = 0; ks < 8; ks++) {
        const uint32_t koff = (uint32_t)(ks * 32);   // 16 halves = 32 bytes
        uint32_t ah[2][4], al[2][4], bh[2][2], bl[2][2];
        LDSM4(ah[0][0], ah[0][1], ah[0][2], ah[0][3], aH0 + koff);
        LDSM4(ah[1][0], ah[1][1], ah[1][2], ah[1][3], aH0 + STEP16 + koff);
        LDSM4(al[0][0], al[0][1], al[0][2], al[0][3], aL0 + koff);
        LDSM4(al[1][0], al[1][1], al[1][2], al[1][3], aL0 + STEP16 + koff);
        LDSM4(bh[0][0], bh[0][1], bh[1][0], bh[1][1], bH0 + koff);
        LDSM4(bl[0][0], bl[0][1], bl[1][0], bl[1][1], bL0 + koff);
#pragma unroll
        for (int mi = 0; mi < 2; mi++)
#pragma unroll
            for (int ni = 0; ni < 2; ni++) {
                mma16816(c[mi][ni], ah[mi], bh[ni]);
                mma16816(c[mi][ni], ah[mi], bl[ni]);
                mma16816(c[mi][ni], al[mi], bh[ni]);
            }
    }
    __syncthreads();   // done with A/B smem; reuse as bounce

    // ---- bounce accumulators to smem ----
    float* bounce = (float*)smem;             // [64][68] floats = 17408 B
#pragma unroll
    for (int mi = 0; mi < 2; mi++) {
        int row = m0 + mi * 16 + lr;
#pragma unroll
        for (int ni = 0; ni < 2; ni++) {
            int col = n0 + ni * 8 + lc;
            bounce[row * BSTRIDE + col]           = c[mi][ni][0];
            bounce[row * BSTRIDE + col + 1]       = c[mi][ni][1];
            bounce[(row + 8) * BSTRIDE + col]     = c[mi][ni][2];
            bounce[(row + 8) * BSTRIDE + col + 1] = c[mi][ni][3];
        }
    }
    __syncthreads();

    // ---- per-row head dots: 2 heads in this col half ----
    if (tid < 128) {
        int r = tid >> 1, hl = tid & 1;       // 64 rows x 2 local heads
        int gr = row0 + r;
        if (gr < N_NODES) {
            int h = (col0 >> 5) + hl;         // global head index
            const float* rowp = &bounce[r * BSTRIDE + hl * 32];
            float ps = 0.f, pt = 0.f;
#pragma unroll
            for (int j = 0; j < 32; j++) {
                float vv = rowp[j];
                ps = fmaf(vv, __ldg(&a_src[h * 32 + j]), ps);
                pt = fmaf(vv, __ldg(&a_trg[h * 32 + j]), pt);
            }
            g_s_src[gr * NH + h] = ps;
            g_s_trg[gr * NH + h] = pt;
        }
    }

    // ---- coalesced fp16 proj copy-out (this CTA's 64-col half) ----
    const int valid = min(CROWS, N_NODES - row0);
    for (int idx = tid; idx < valid * 32; idx += 256) {   // 32 half2 per row
        int r = idx >> 5, c2i = idx & 31;
        float2 f = make_float2(bounce[r * BSTRIDE + c2i * 2],
                               bounce[r * BSTRIDE + c2i * 2 + 1]);
        ((__half2*)&g_projh[(size_t)(row0 + r) * FIN + col0])[c2i] = __float22half2_rn(f);
    }
}

// ---------------- kernel: global max over leaky edge scores --------------
__global__ void k_edge_max(const int* __restrict__ ei, int E) {
    float m = __uint_as_float(0xFF800000u);
    int i = blockIdx.x * blockDim.x + threadIdx.x;
    int stride = gridDim.x * blockDim.x;
    for (; i < E; i += stride) {
        int src = ei[i];
        int trg = ei[E + i];
        float4 ss = *(const float4*)&g_s_src[src * NH];
        float4 st = *(const float4*)&g_s_trg[trg * NH];
        float v;
        v = ss.x + st.x; v = v > 0.f ? v : LEAKY * v; m = fmaxf(m, v);
        v = ss.y + st.y; v = v > 0.f ? v : LEAKY * v; m = fmaxf(m, v);
        v = ss.z + st.z; v = v > 0.f ? v : LEAKY * v; m = fmaxf(m, v);
        v = ss.w + st.w; v = v > 0.f ? v : LEAKY * v; m = fmaxf(m, v);
    }
#pragma unroll
    for (int o = 16; o >= 1; o >>= 1) m = fmaxf(m, __shfl_xor_sync(0xffffffffu, m, o));
    __shared__ float sm[8];
    int lane = threadIdx.x & 31, warp = threadIdx.x >> 5;
    if (lane == 0) sm[warp] = m;
    __syncthreads();
    if (warp == 0) {
        m = (lane < 8) ? sm[lane] : __uint_as_float(0xFF800000u);
#pragma unroll
        for (int o = 4; o >= 1; o >>= 1) m = fmaxf(m, __shfl_xor_sync(0xffffffffu, m, o));
        if (lane == 0) atomicMaxFloat(&g_max, m);
    }
}

// ---------------- kernel: SINGLE-PASS aggregate + skip + bias + ELU ------
__global__ __launch_bounds__(256) void k_node(const float* __restrict__ x,
                                              const float* __restrict__ bias,
                                              float* __restrict__ out) {
    int n = (blockIdx.x * blockDim.x + threadIdx.x) >> 5;
    if (n >= N_NODES) return;
    const int lane = threadIdx.x & 31;
    const int head = lane >> 3;
    const int start = g_off[n];
    const int deg = g_cnt[n];
    const float gm = g_max;
    const float st_h = g_s_trg[n * NH + head];

    float4 acc = make_float4(0.f, 0.f, 0.f, 0.f);
    float d = 0.f;

    int k = 0;
    for (; k + 3 < deg; k += 4) {
        int s0 = g_esrc[start + k];
        int s1 = g_esrc[start + k + 1];
        int s2 = g_esrc[start + k + 2];
        int s3 = g_esrc[start + k + 3];
        float sa = g_s_src[s0 * NH + head];
        float sb = g_s_src[s1 * NH + head];
        float sc = g_s_src[s2 * NH + head];
        float sd = g_s_src[s3 * NH + head];
        uint2 ha = *(const uint2*)&g_projh[(size_t)s0 * FIN + lane * 4];
        uint2 hb = *(const uint2*)&g_projh[(size_t)s1 * FIN + lane * 4];
        uint2 hc = *(const uint2*)&g_projh[(size_t)s2 * FIN + lane * 4];
        uint2 hd = *(const uint2*)&g_projh[(size_t)s3 * FIN + lane * 4];
        float va = sa + st_h; va = va > 0.f ? va : LEAKY * va;
        float vb = sb + st_h; vb = vb > 0.f ? vb : LEAKY * vb;
        float vc = sc + st_h; vc = vc > 0.f ? vc : LEAKY * vc;
        float vd = sd + st_h; vd = vd > 0.f ? vd : LEAKY * vd;
        float ea = expf(va - gm), eb = expf(vb - gm);
        float ec = expf(vc - gm), ed = expf(vd - gm);
        d += ea + eb + ec + ed;
        float2 pa0 = __half22float2(*(const __half2*)&ha.x);
        float2 pa1 = __half22float2(*(const __half2*)&ha.y);
        float2 pb0 = __half22float2(*(const __half2*)&hb.x);
        float2 pb1 = __half22float2(*(const __half2*)&hb.y);
        float2 pc0 = __half22float2(*(const __half2*)&hc.x);
        float2 pc1 = __half22float2(*(const __half2*)&hc.y);
        float2 pd0 = __half22float2(*(const __half2*)&hd.x);
        float2 pd1 = __half22float2(*(const __half2*)&hd.y);
        acc.x = fmaf(pa0.x, ea, acc.x); acc.x = fmaf(pb0.x, eb, acc.x);
        acc.x = fmaf(pc0.x, ec, acc.x); acc.x = fmaf(pd0.x, ed, acc.x);
        acc.y = fmaf(pa0.y, ea, acc.y); acc.y = fmaf(pb0.y, eb, acc.y);
        acc.y = fmaf(pc0.y, ec, acc.y); acc.y = fmaf(pd0.y, ed, acc.y);
        acc.z = fmaf(pa1.x, ea, acc.z); acc.z = fmaf(pb1.x, eb, acc.z);
        acc.z = fmaf(pc1.x, ec, acc.z); acc.z = fmaf(pd1.x, ed, acc.z);
        acc.w = fmaf(pa1.y, ea, acc.w); acc.w = fmaf(pb1.y, eb, acc.w);
        acc.w = fmaf(pc1.y, ec, acc.w); acc.w = fmaf(pd1.y, ed, acc.w);
    }
    for (; k < deg; k++) {
        int s0 = g_esrc[start + k];
        float sa = g_s_src[s0 * NH + head];
        uint2 ha = *(const uint2*)&g_projh[(size_t)s0 * FIN + lane * 4];
        float va = sa + st_h; va = va > 0.f ? va : LEAKY * va;
        float ea = expf(va - gm);
        d += ea;
        float2 pa0 = __half22float2(*(const __half2*)&ha.x);
        float2 pa1 = __half22float2(*(const __half2*)&ha.y);
        acc.x = fmaf(pa0.x, ea, acc.x);
        acc.y = fmaf(pa0.y, ea, acc.y);
        acc.z = fmaf(pa1.x, ea, acc.z);
        acc.w = fmaf(pa1.y, ea, acc.w);
    }

    const float rd = 1.f / (d + 1e-16f);
    float4 xb = *(const float4*)&x[n * FIN + lane * 4];
    float4 bb = *(const float4*)&bias[lane * 4];
    float4 r;
    r.x = fmaf(acc.x, rd, xb.x + bb.x); r.x = r.x > 0.f ? r.x : expm1f(r.x);
    r.y = fmaf(acc.y, rd, xb.y + bb.y); r.y = r.y > 0.f ? r.y : expm1f(r.y);
    r.z = fmaf(acc.z, rd, xb.z + bb.z); r.z = r.z > 0.f ? r.z : expm1f(r.z);
    r.w = fmaf(acc.w, rd, xb.w + bb.w); r.w = r.w > 0.f ? r.w : expm1f(r.w);
    *(float4*)&out[n * FIN + lane * 4] = r;
}

// ---------------- launch: graph-forked CSR build || GEMM -----------------
extern "C" void kernel_launch(void* const* d_in, const int* in_sizes, int n_in,
                              void* d_out, int out_size) {
    const float* x     = (const float*)d_in[0];
    const int*   ei    = (const int*)d_in[1];   // JAX x64 disabled: int32
    const float* W     = (const float*)d_in[2];
    const float* a_src = (const float*)d_in[3];
    const float* a_trg = (const float*)d_in[4];
    const float* bias  = (const float*)d_in[5];
    float* out = (float*)d_out;

    const int E = in_sizes[1] / 2;

    static cudaStream_t s2 = nullptr;
    static cudaEvent_t evFork = nullptr, evJoin = nullptr;
    if (s2 == nullptr) {
        cudaStreamCreateWithFlags(&s2, cudaStreamNonBlocking);
        cudaEventCreateWithFlags(&evFork, cudaEventDisableTiming);
        cudaEventCreateWithFlags(&evJoin, cudaEventDisableTiming);
        cudaFuncSetAttribute(k_gemm_mma, cudaFuncAttributeMaxDynamicSharedMemorySize, GEMM_SMEM);
    }

    k_init<<<NB_CHUNKS, 256>>>(W);

    // fork: full CSR build (count/offsets/scatter) on s2, GEMM on main
    cudaEventRecord(evFork, 0);
    cudaStreamWaitEvent(s2, evFork, 0);
    k_count<<<(E + 255) / 256, 256, 0, s2>>>(ei, E);
    k_offsets<<<NB_CHUNKS, 256, 0, s2>>>();
    k_scatter<<<(E + 255) / 256, 256, 0, s2>>>(ei, E);
    cudaEventRecord(evJoin, s2);

    dim3 ggrid((N_NODES + CROWS - 1) / CROWS, FIN / CCOLS);
    k_gemm_mma<<<ggrid, 256, GEMM_SMEM>>>(x, a_src, a_trg);

    // max needs scores (GEMM); node needs max + CSR
    k_edge_max<<<1024, 256>>>(ei, E);
    cudaStreamWaitEvent(0, evJoin, 0);
    k_node<<<(N_NODES * 32 + 255) / 256, 256>>>(x, bias, out);
}